// round 2
// baseline (speedup 1.0000x reference)
#include <cuda_runtime.h>
#include <cstdint>
#include <cstddef>

#define B 8
#define L 1024
#define H 16
#define DK 64
#define DM 1024
#define BH (B*H)

// ---------------- scratch (device globals; no allocations allowed) ----------
__device__ float g_Q[(size_t)BH * L * DK];      // [bh][l][64]
__device__ float g_K[(size_t)BH * L * DK];
__device__ float g_V[(size_t)BH * L * DK];
__device__ float g_ctx[(size_t)BH * L * DK];
__device__ float g_preln[(size_t)B * L * DM];   // O + X before layernorm
__device__ int   g_mask_u8;                     // 1 if mask is byte-packed

// ---------------- mask dtype detection -------------------------------------
// jnp bool may arrive as uint8 (1 byte) or int32 (4 bytes). If int32, every
// 32-bit word is 0 or 1. If uint8, random 0/1 bytes make words > 1 almost
// surely within 16384 words. All-False mask => either interpretation reads 0.
__global__ void detect_mask_kernel(const unsigned int* __restrict__ m)
{
    __shared__ int s_any;
    if (threadIdx.x == 0) s_any = 0;
    __syncthreads();
    int any = 0;
    for (int i = threadIdx.x; i < 16384; i += 256)
        if (m[i] > 1u) any = 1;
    if (any) atomicOr(&s_any, 1);
    __syncthreads();
    if (threadIdx.x == 0) g_mask_u8 = s_any;
}

// ---------------- QKV projection: 3x SGEMM M=8192 N=1024 K=1024 ------------
// 128x128 tile, BK=8, 256 threads, 8x8 per thread. Output scattered to
// [bh][l][d] layout for the attention kernel.
__global__ __launch_bounds__(256) void qkv_kernel(
    const float* __restrict__ X,
    const float* __restrict__ Wq,
    const float* __restrict__ Wk,
    const float* __restrict__ Wv)
{
    const float* W   = (blockIdx.z == 0) ? Wq : (blockIdx.z == 1) ? Wk : Wv;
    float*       Out = (blockIdx.z == 0) ? g_Q : (blockIdx.z == 1) ? g_K : g_V;

    __shared__ float As[8][128];
    __shared__ float Bs[8][128];

    const int tid  = threadIdx.x;
    const int row0 = blockIdx.y * 128;
    const int col0 = blockIdx.x * 128;

    const int arow = tid >> 1, ac4 = (tid & 1) * 4;
    const int brow = tid >> 5, bc4 = (tid & 31) * 4;
    const int ty = tid >> 4, tx = tid & 15;

    float acc[8][8];
#pragma unroll
    for (int i = 0; i < 8; i++)
#pragma unroll
        for (int j = 0; j < 8; j++) acc[i][j] = 0.f;

    for (int k0 = 0; k0 < DM; k0 += 8) {
        float4 av = *(const float4*)(X + (size_t)(row0 + arow) * DM + k0 + ac4);
        float4 bv = *(const float4*)(W + (size_t)(k0 + brow) * DM + col0 + bc4);
        __syncthreads();
        As[ac4 + 0][arow] = av.x;
        As[ac4 + 1][arow] = av.y;
        As[ac4 + 2][arow] = av.z;
        As[ac4 + 3][arow] = av.w;
        *(float4*)&Bs[brow][bc4] = bv;
        __syncthreads();
#pragma unroll
        for (int k = 0; k < 8; k++) {
            float4 a1 = *(const float4*)&As[k][ty * 4];
            float4 a2 = *(const float4*)&As[k][64 + ty * 4];
            float4 b1 = *(const float4*)&Bs[k][tx * 4];
            float4 b2 = *(const float4*)&Bs[k][64 + tx * 4];
            float a[8] = {a1.x, a1.y, a1.z, a1.w, a2.x, a2.y, a2.z, a2.w};
            float bb[8] = {b1.x, b1.y, b1.z, b1.w, b2.x, b2.y, b2.z, b2.w};
#pragma unroll
            for (int i = 0; i < 8; i++)
#pragma unroll
                for (int j = 0; j < 8; j++) acc[i][j] += a[i] * bb[j];
        }
    }

#pragma unroll
    for (int i = 0; i < 8; i++) {
        int r  = row0 + ((i < 4) ? (ty * 4 + i) : (64 + ty * 4 + (i - 4)));
        int b_ = r >> 10, l_ = r & 1023;
#pragma unroll
        for (int j = 0; j < 8; j++) {
            int c  = col0 + ((j < 4) ? (tx * 4 + j) : (64 + tx * 4 + (j - 4)));
            int h_ = c >> 6, d_ = c & 63;
            Out[(((size_t)(b_ * H + h_)) * L + l_) * DK + d_] = acc[i][j];
        }
    }
}

// ---------------- fused attention: scores + mask + softmax + context --------
// One block per (bh, 16 query rows). S tile [16][1024] in smem (row pad 1025),
// K/V streamed in 64-row chunks (row pad 68 for float4 conflict-free loads),
// Q held in 16 float4 registers per thread.
__global__ __launch_bounds__(256) void attn_kernel(
    const void* __restrict__ mask, float* __restrict__ attn_out)
{
    extern __shared__ float sm[];
    float* S   = sm;                       // 16 * 1025
    float* Qs  = sm + 16 * 1025;           // 16 * 68
    float* KVs = Qs + 16 * 68;             // 64 * 68

    const int tid = threadIdx.x;
    const int bh  = blockIdx.y;
    const int b_  = bh >> 4;
    const int q0  = blockIdx.x * 16;
    const int u8  = g_mask_u8;

    const float* Qp = g_Q + (size_t)bh * L * DK;
    const float* Kp = g_K + (size_t)bh * L * DK;
    const float* Vp = g_V + (size_t)bh * L * DK;

    for (int idx = tid; idx < 16 * DK; idx += 256) {
        int r = idx >> 6, d = idx & 63;
        Qs[r * 68 + d] = Qp[(size_t)(q0 + r) * DK + d];
    }
    __syncthreads();

    const int row = tid >> 4;   // 0..15 query row within tile
    const int kl  = tid & 15;

    float4 qreg[16];
#pragma unroll
    for (int i = 0; i < 16; i++) qreg[i] = *(const float4*)&Qs[row * 68 + i * 4];

    const float scale = 0.125f;  // 1/sqrt(64)

    // ---- scores ----
    for (int kc = 0; kc < L; kc += 64) {
        __syncthreads();
        for (int idx = tid; idx < 64 * DK; idx += 256) {
            int r = idx >> 6, d = idx & 63;
            KVs[r * 68 + d] = Kp[(size_t)(kc + r) * DK + d];
        }
        __syncthreads();
#pragma unroll
        for (int e = 0; e < 4; e++) {
            int key = kl + 16 * e;
            const float4* k4p = (const float4*)&KVs[key * 68];
            float s = 0.f;
#pragma unroll
            for (int i = 0; i < 16; i++) {
                float4 k4 = k4p[i];
                s += qreg[i].x * k4.x + qreg[i].y * k4.y +
                     qreg[i].z * k4.z + qreg[i].w * k4.w;
            }
            int gq = q0 + row, gk = kc + key;
            size_t midx = ((size_t)b_ * L + gq) * L + gk;
            bool msk = u8 ? (((const unsigned char*)mask)[midx] != 0)
                          : (((const int*)mask)[midx] != 0);
            S[row * 1025 + gk] = msk ? -1e9f : s * scale;
        }
    }
    __syncthreads();

    // ---- softmax (16 threads per row, each scans 64 elems, shfl reduce) ----
    float mx = -3.4e38f;
    for (int k = 0; k < 64; k++) mx = fmaxf(mx, S[row * 1025 + kl + 16 * k]);
#pragma unroll
    for (int off = 8; off; off >>= 1)
        mx = fmaxf(mx, __shfl_xor_sync(0xffffffffu, mx, off));
    float sum = 0.f;
    for (int k = 0; k < 64; k++) {
        int c = kl + 16 * k;
        float e_ = __expf(S[row * 1025 + c] - mx);
        S[row * 1025 + c] = e_;
        sum += e_;
    }
#pragma unroll
    for (int off = 8; off; off >>= 1)
        sum += __shfl_xor_sync(0xffffffffu, sum, off);
    float inv = 1.f / sum;
    for (int k = 0; k < 64; k++) S[row * 1025 + kl + 16 * k] *= inv;
    __syncthreads();

    // ---- attn probabilities out (coalesced) ----
    if (attn_out) {
        for (int idx = tid; idx < 16 * L; idx += 256) {
            int r = idx >> 10, c = idx & 1023;
            attn_out[((size_t)bh * L + q0 + r) * L + c] = S[r * 1025 + c];
        }
    }

    // ---- context: C[16][64] = S[16][1024] @ V[1024][64] --------------------
    float4 acc = make_float4(0.f, 0.f, 0.f, 0.f);
    const int dl = (tid & 15) * 4;
    for (int kc = 0; kc < L; kc += 64) {
        __syncthreads();
        for (int idx = tid; idx < 64 * DK; idx += 256) {
            int r = idx >> 6, d = idx & 63;
            KVs[r * 68 + d] = Vp[(size_t)(kc + r) * DK + d];
        }
        __syncthreads();
#pragma unroll 8
        for (int k = 0; k < 64; k++) {
            float p = S[row * 1025 + kc + k];
            float4 v = *(const float4*)&KVs[k * 68 + dl];
            acc.x += p * v.x;
            acc.y += p * v.y;
            acc.z += p * v.z;
            acc.w += p * v.w;
        }
    }
    *(float4*)&g_ctx[((size_t)bh * L + q0 + row) * DK + dl] = acc;
}

// ---------------- output projection + residual ------------------------------
// g_preln = ctx2d @ W_O + X ; ctx2d[r][c] gathered from g_ctx's [bh][l][d].
__global__ __launch_bounds__(256) void oproj_kernel(
    const float* __restrict__ X, const float* __restrict__ Wo)
{
    __shared__ float As[8][128];
    __shared__ float Bs[8][128];

    const int tid  = threadIdx.x;
    const int row0 = blockIdx.y * 128;
    const int col0 = blockIdx.x * 128;

    const int arow = tid >> 1, ac4 = (tid & 1) * 4;
    const int brow = tid >> 5, bc4 = (tid & 31) * 4;
    const int ty = tid >> 4, tx = tid & 15;

    float acc[8][8];
#pragma unroll
    for (int i = 0; i < 8; i++)
#pragma unroll
        for (int j = 0; j < 8; j++) acc[i][j] = 0.f;

    const int r_a = row0 + arow;
    const int ba_ = r_a >> 10, la_ = r_a & 1023;

    for (int k0 = 0; k0 < DM; k0 += 8) {
        int c  = k0 + ac4;
        int h_ = c >> 6, d_ = c & 63;   // float4 never crosses a head boundary
        float4 av = *(const float4*)&g_ctx[(((size_t)(ba_ * H + h_)) * L + la_) * DK + d_];
        float4 bv = *(const float4*)(Wo + (size_t)(k0 + brow) * DM + col0 + bc4);
        __syncthreads();
        As[ac4 + 0][arow] = av.x;
        As[ac4 + 1][arow] = av.y;
        As[ac4 + 2][arow] = av.z;
        As[ac4 + 3][arow] = av.w;
        *(float4*)&Bs[brow][bc4] = bv;
        __syncthreads();
#pragma unroll
        for (int k = 0; k < 8; k++) {
            float4 a1 = *(const float4*)&As[k][ty * 4];
            float4 a2 = *(const float4*)&As[k][64 + ty * 4];
            float4 b1 = *(const float4*)&Bs[k][tx * 4];
            float4 b2 = *(const float4*)&Bs[k][64 + tx * 4];
            float a[8] = {a1.x, a1.y, a1.z, a1.w, a2.x, a2.y, a2.z, a2.w};
            float bb[8] = {b1.x, b1.y, b1.z, b1.w, b2.x, b2.y, b2.z, b2.w};
#pragma unroll
            for (int i = 0; i < 8; i++)
#pragma unroll
                for (int j = 0; j < 8; j++) acc[i][j] += a[i] * bb[j];
        }
    }

#pragma unroll
    for (int i = 0; i < 8; i++) {
        int r = row0 + ((i < 4) ? (ty * 4 + i) : (64 + ty * 4 + (i - 4)));
#pragma unroll
        for (int j = 0; j < 8; j++) {
            int c = col0 + ((j < 4) ? (tx * 4 + j) : (64 + tx * 4 + (j - 4)));
            g_preln[(size_t)r * DM + c] = acc[i][j] + X[(size_t)r * DM + c];
        }
    }
}

// ---------------- layernorm over last dim (1024) ----------------------------
__global__ __launch_bounds__(256) void ln_kernel(
    const float* __restrict__ gamma, const float* __restrict__ beta,
    float* __restrict__ out)
{
    __shared__ float red[18];
    const int r = blockIdx.x, tid = threadIdx.x;
    const float4* x4 = (const float4*)(g_preln + (size_t)r * DM);
    float4 v = x4[tid];

    float s = v.x + v.y + v.z + v.w;
#pragma unroll
    for (int off = 16; off; off >>= 1) s += __shfl_xor_sync(0xffffffffu, s, off);
    if ((tid & 31) == 0) red[tid >> 5] = s;
    __syncthreads();
    if (tid == 0) {
        float t = 0.f;
        for (int i = 0; i < 8; i++) t += red[i];
        red[16] = t * (1.f / 1024.f);
    }
    __syncthreads();
    float mean = red[16];

    float dx = v.x - mean, dy = v.y - mean, dz = v.z - mean, dw = v.w - mean;
    float ss = dx * dx + dy * dy + dz * dz + dw * dw;
#pragma unroll
    for (int off = 16; off; off >>= 1) ss += __shfl_xor_sync(0xffffffffu, ss, off);
    if ((tid & 31) == 0) red[8 + (tid >> 5)] = ss;
    __syncthreads();
    if (tid == 0) {
        float t = 0.f;
        for (int i = 0; i < 8; i++) t += red[8 + i];
        red[17] = rsqrtf(t * (1.f / 1024.f) + 1e-6f);
    }
    __syncthreads();
    float rs = red[17];

    float4 g = ((const float4*)gamma)[tid];
    float4 bb = ((const float4*)beta)[tid];
    float4 o;
    o.x = dx * rs * g.x + bb.x;
    o.y = dy * rs * g.y + bb.y;
    o.z = dz * rs * g.z + bb.z;
    o.w = dw * rs * g.w + bb.w;

    float* op = out ? (out + (size_t)r * DM) : (g_preln + (size_t)r * DM);
    ((float4*)op)[tid] = o;
}

// ---------------- launch -----------------------------------------------------
extern "C" void kernel_launch(void* const* d_in, const int* in_sizes, int n_in,
                              void* d_out, int out_size)
{
    const float* X     = (const float*)d_in[0];
    const void*  mask  = d_in[1];
    const float* Wq    = (const float*)d_in[2];
    const float* Wk    = (const float*)d_in[3];
    const float* Wv    = (const float*)d_in[4];
    const float* Wo    = (const float*)d_in[5];
    const float* gamma = (const float*)d_in[6];
    const float* beta  = (const float*)d_in[7];

    const long long LNN = (long long)B * L * DM;  // 8,388,608
    const long long ATT = (long long)BH * L * L;  // 134,217,728

    float* out_ln = nullptr;
    float* out_attn = nullptr;
    long long os = (long long)out_size;
    if (os >= LNN + ATT) {
        out_ln = (float*)d_out;
        out_attn = (float*)d_out + LNN;
    } else if (os == ATT) {
        out_attn = (float*)d_out;
    } else {
        out_ln = (float*)d_out;
    }

    detect_mask_kernel<<<1, 256>>>((const unsigned int*)mask);
    qkv_kernel<<<dim3(8, 64, 3), 256>>>(X, Wq, Wk, Wv);

    size_t smem = (size_t)(16 * 1025 + 16 * 68 + 64 * 68) * sizeof(float);
    cudaFuncSetAttribute(attn_kernel,
                         cudaFuncAttributeMaxDynamicSharedMemorySize, (int)smem);
    attn_kernel<<<dim3(L / 16, BH), 256, smem>>>(mask, out_attn);

    oproj_kernel<<<dim3(8, 64), 256>>>(X, Wo);
    ln_kernel<<<B * L, 256>>>(gamma, beta, out_ln);
}

// round 4
// speedup vs baseline: 1.6743x; 1.6743x over previous
#include <cuda_runtime.h>
#include <cstdint>
#include <cstddef>

#define B 8
#define L 1024
#define H 16
#define DK 64
#define DM 1024
#define BH (B*H)
#define SP 1028   // S row stride: multiple of 4 floats -> 16B-aligned rows

// ---------------- scratch (device globals; no allocations allowed) ----------
__device__ float g_Q[(size_t)BH * L * DK];      // [bh][l][64]
__device__ float g_K[(size_t)BH * L * DK];
__device__ float g_V[(size_t)BH * L * DK];
__device__ float g_ctx[(size_t)BH * L * DK];
__device__ float g_preln[(size_t)B * L * DM];
__device__ int   g_mask_u8;

// ---------------- mask dtype detection -------------------------------------
__global__ void detect_mask_kernel(const unsigned int* __restrict__ m)
{
    __shared__ int s_any;
    if (threadIdx.x == 0) s_any = 0;
    __syncthreads();
    int any = 0;
    for (int i = threadIdx.x; i < 16384; i += 256)
        if (m[i] > 1u) any = 1;
    if (any) atomicOr(&s_any, 1);
    __syncthreads();
    if (threadIdx.x == 0) g_mask_u8 = s_any;
}

// ---------------- QKV projection: double-buffered SGEMM --------------------
__global__ __launch_bounds__(256) void qkv_kernel(
    const float* __restrict__ X,
    const float* __restrict__ Wq,
    const float* __restrict__ Wk,
    const float* __restrict__ Wv)
{
    const float* W   = (blockIdx.z == 0) ? Wq : (blockIdx.z == 1) ? Wk : Wv;
    float*       Out = (blockIdx.z == 0) ? g_Q : (blockIdx.z == 1) ? g_K : g_V;

    __shared__ float As[2][8][128];
    __shared__ float Bs[2][8][128];

    const int tid  = threadIdx.x;
    const int row0 = blockIdx.y * 128;
    const int col0 = blockIdx.x * 128;

    const int arow = tid >> 1, ac4 = (tid & 1) * 4;
    const int brow = tid >> 5, bc4 = (tid & 31) * 4;
    const int ty = tid >> 4, tx = tid & 15;

    float acc[8][8];
#pragma unroll
    for (int i = 0; i < 8; i++)
#pragma unroll
        for (int j = 0; j < 8; j++) acc[i][j] = 0.f;

    const float* Aptr = X + (size_t)(row0 + arow) * DM + ac4;
    const float* Bptr = W + (size_t)brow * DM + col0 + bc4;

    {
        float4 av = *(const float4*)(Aptr);
        float4 bv = *(const float4*)(Bptr);
        As[0][ac4 + 0][arow] = av.x;
        As[0][ac4 + 1][arow] = av.y;
        As[0][ac4 + 2][arow] = av.z;
        As[0][ac4 + 3][arow] = av.w;
        *(float4*)&Bs[0][brow][bc4] = bv;
    }
    __syncthreads();

    int buf = 0;
    for (int k0 = 0; k0 < DM; k0 += 8) {
        float4 av, bv;
        const bool nxt = (k0 + 8) < DM;
        if (nxt) {
            av = *(const float4*)(Aptr + k0 + 8);
            bv = *(const float4*)(Bptr + (size_t)(k0 + 8) * DM);
        }
#pragma unroll
        for (int k = 0; k < 8; k++) {
            float4 a1 = *(const float4*)&As[buf][k][ty * 4];
            float4 a2 = *(const float4*)&As[buf][k][64 + ty * 4];
            float4 b1 = *(const float4*)&Bs[buf][k][tx * 4];
            float4 b2 = *(const float4*)&Bs[buf][k][64 + tx * 4];
            float a[8] = {a1.x, a1.y, a1.z, a1.w, a2.x, a2.y, a2.z, a2.w};
            float bb[8] = {b1.x, b1.y, b1.z, b1.w, b2.x, b2.y, b2.z, b2.w};
#pragma unroll
            for (int i = 0; i < 8; i++)
#pragma unroll
                for (int j = 0; j < 8; j++) acc[i][j] += a[i] * bb[j];
        }
        if (nxt) {
            As[buf ^ 1][ac4 + 0][arow] = av.x;
            As[buf ^ 1][ac4 + 1][arow] = av.y;
            As[buf ^ 1][ac4 + 2][arow] = av.z;
            As[buf ^ 1][ac4 + 3][arow] = av.w;
            *(float4*)&Bs[buf ^ 1][brow][bc4] = bv;
        }
        __syncthreads();
        buf ^= 1;
    }

#pragma unroll
    for (int i = 0; i < 8; i++) {
        int r  = row0 + ((i < 4) ? (ty * 4 + i) : (64 + ty * 4 + (i - 4)));
        int b_ = r >> 10, l_ = r & 1023;
#pragma unroll
        for (int g = 0; g < 2; g++) {
            int c0 = col0 + g * 64 + tx * 4;
            int h_ = c0 >> 6, d_ = c0 & 63;
            float4 o;
            o.x = acc[i][g * 4 + 0];
            o.y = acc[i][g * 4 + 1];
            o.z = acc[i][g * 4 + 2];
            o.w = acc[i][g * 4 + 3];
            *(float4*)&Out[(((size_t)(b_ * H + h_)) * L + l_) * DK + d_] = o;
        }
    }
}

// ---------------- fused attention -------------------------------------------
__global__ __launch_bounds__(256, 2) void attn_kernel(
    const void* __restrict__ mask, float* __restrict__ attn_out)
{
    extern __shared__ float sm[];
    float* S  = sm;                    // 16 * SP
    float* KV = sm + 16 * SP;          // 2 * 64 * 68

    const int tid = threadIdx.x;
    const int bh  = blockIdx.y;
    const int b_  = bh >> 4;
    const int q0  = blockIdx.x * 16;
    const int u8  = g_mask_u8;

    const float* Qp = g_Q + (size_t)bh * L * DK;
    const float* Kp = g_K + (size_t)bh * L * DK;
    const float* Vp = g_V + (size_t)bh * L * DK;

    const int r2 = tid >> 5;          // warp id, row pair
    const int dh = (tid >> 4) & 1;    // d half
    const int kl = tid & 15;
    const int rA = 2 * r2, rB = 2 * r2 + 1;

    const int li_r[4] = { (tid + 0) >> 4, (tid + 256) >> 4,
                          (tid + 512) >> 4, (tid + 768) >> 4 };
    const int li_d = (tid & 15) * 4;

    float4 qa[8], qb[8];
#pragma unroll
    for (int i = 0; i < 8; i++) {
        qa[i] = *(const float4*)(Qp + (size_t)(q0 + rA) * DK + dh * 32 + i * 4);
        qb[i] = *(const float4*)(Qp + (size_t)(q0 + rB) * DK + dh * 32 + i * 4);
    }

    // ---- score phase ----
    {
#pragma unroll
        for (int t = 0; t < 4; t++) {
            float4 v = *(const float4*)(Kp + (size_t)li_r[t] * DK + li_d);
            *(float4*)&KV[li_r[t] * 68 + li_d] = v;
        }
        __syncthreads();
        int buf = 0;
        for (int kc = 0; kc < L; kc += 64) {
            float4 pre[4];
            const bool nxt = (kc + 64) < L;
            if (nxt) {
#pragma unroll
                for (int t = 0; t < 4; t++)
                    pre[t] = *(const float4*)(Kp + (size_t)(kc + 64 + li_r[t]) * DK + li_d);
            }
            const float* KB = KV + buf * (64 * 68);
#pragma unroll
            for (int e = 0; e < 4; e++) {
                int key = e * 16 + kl;
                const float4* kp = (const float4*)&KB[key * 68 + dh * 32];
                float sa = 0.f, sb = 0.f;
#pragma unroll
                for (int i = 0; i < 8; i++) {
                    float4 k4 = kp[i];
                    sa += qa[i].x * k4.x + qa[i].y * k4.y + qa[i].z * k4.z + qa[i].w * k4.w;
                    sb += qb[i].x * k4.x + qb[i].y * k4.y + qb[i].z * k4.z + qb[i].w * k4.w;
                }
                sa += __shfl_xor_sync(0xffffffffu, sa, 16);
                sb += __shfl_xor_sync(0xffffffffu, sb, 16);
                int row = dh ? rB : rA;
                float sv = dh ? sb : sa;
                int gk = kc + key;
                size_t midx = ((size_t)b_ * L + q0 + row) * L + gk;
                bool msk = u8 ? (((const unsigned char*)mask)[midx] != 0)
                              : (((const int*)mask)[midx] != 0);
                S[row * SP + gk] = msk ? -1e9f : sv * 0.125f;
            }
            if (nxt) {
                float* KN = KV + (buf ^ 1) * (64 * 68);
#pragma unroll
                for (int t = 0; t < 4; t++)
                    *(float4*)&KN[li_r[t] * 68 + li_d] = pre[t];
            }
            __syncthreads();
            buf ^= 1;
        }
    }

    // ---- softmax (16 threads per row) ----
    {
        const int row = tid >> 4;
        const int c0  = tid & 15;
        float mx = -3.4e38f;
        for (int k = 0; k < 64; k++) mx = fmaxf(mx, S[row * SP + c0 + 16 * k]);
#pragma unroll
        for (int off = 8; off; off >>= 1)
            mx = fmaxf(mx, __shfl_xor_sync(0xffffffffu, mx, off));
        float sum = 0.f;
        for (int k = 0; k < 64; k++) {
            int c = c0 + 16 * k;
            float e_ = __expf(S[row * SP + c] - mx);
            S[row * SP + c] = e_;
            sum += e_;
        }
#pragma unroll
        for (int off = 8; off; off >>= 1)
            sum += __shfl_xor_sync(0xffffffffu, sum, off);
        float inv = 1.f / sum;
        for (int k = 0; k < 64; k++) S[row * SP + c0 + 16 * k] *= inv;
    }
    __syncthreads();

    // ---- attn probabilities out ----
    if (attn_out) {
        for (int idx = tid; idx < 16 * L; idx += 256) {
            int r = idx >> 10, c = idx & 1023;
            attn_out[((size_t)bh * L + q0 + r) * L + c] = S[r * SP + c];
        }
    }

    // ---- context: C[16][64] = S @ V ----
    {
        const int kh = (tid >> 4) & 1;
        const int dl = (tid & 15) * 4;
        float4 accA = make_float4(0.f, 0.f, 0.f, 0.f);
        float4 accB = make_float4(0.f, 0.f, 0.f, 0.f);

#pragma unroll
        for (int t = 0; t < 4; t++) {
            float4 v = *(const float4*)(Vp + (size_t)li_r[t] * DK + li_d);
            *(float4*)&KV[li_r[t] * 68 + li_d] = v;
        }
        __syncthreads();
        int buf = 0;
        for (int kc = 0; kc < L; kc += 64) {
            float4 pre[4];
            const bool nxt = (kc + 64) < L;
            if (nxt) {
#pragma unroll
                for (int t = 0; t < 4; t++)
                    pre[t] = *(const float4*)(Vp + (size_t)(kc + 64 + li_r[t]) * DK + li_d);
            }
            const float* VB = KV + buf * (64 * 68);
#pragma unroll
            for (int g = 0; g < 8; g++) {
                int k0 = kh * 32 + g * 4;
                float4 pA = *(const float4*)&S[rA * SP + kc + k0];
                float4 pB = *(const float4*)&S[rB * SP + kc + k0];
                float4 v0 = *(const float4*)&VB[(k0 + 0) * 68 + dl];
                float4 v1 = *(const float4*)&VB[(k0 + 1) * 68 + dl];
                float4 v2 = *(const float4*)&VB[(k0 + 2) * 68 + dl];
                float4 v3 = *(const float4*)&VB[(k0 + 3) * 68 + dl];
                accA.x += pA.x * v0.x + pA.y * v1.x + pA.z * v2.x + pA.w * v3.x;
                accA.y += pA.x * v0.y + pA.y * v1.y + pA.z * v2.y + pA.w * v3.y;
                accA.z += pA.x * v0.z + pA.y * v1.z + pA.z * v2.z + pA.w * v3.z;
                accA.w += pA.x * v0.w + pA.y * v1.w + pA.z * v2.w + pA.w * v3.w;
                accB.x += pB.x * v0.x + pB.y * v1.x + pB.z * v2.x + pB.w * v3.x;
                accB.y += pB.x * v0.y + pB.y * v1.y + pB.z * v2.y + pB.w * v3.y;
                accB.z += pB.x * v0.z + pB.y * v1.z + pB.z * v2.z + pB.w * v3.z;
                accB.w += pB.x * v0.w + pB.y * v1.w + pB.z * v2.w + pB.w * v3.w;
            }
            if (nxt) {
                float* VN = KV + (buf ^ 1) * (64 * 68);
#pragma unroll
                for (int t = 0; t < 4; t++)
                    *(float4*)&VN[li_r[t] * 68 + li_d] = pre[t];
            }
            __syncthreads();
            buf ^= 1;
        }

        accA.x += __shfl_xor_sync(0xffffffffu, accA.x, 16);
        accA.y += __shfl_xor_sync(0xffffffffu, accA.y, 16);
        accA.z += __shfl_xor_sync(0xffffffffu, accA.z, 16);
        accA.w += __shfl_xor_sync(0xffffffffu, accA.w, 16);
        accB.x += __shfl_xor_sync(0xffffffffu, accB.x, 16);
        accB.y += __shfl_xor_sync(0xffffffffu, accB.y, 16);
        accB.z += __shfl_xor_sync(0xffffffffu, accB.z, 16);
        accB.w += __shfl_xor_sync(0xffffffffu, accB.w, 16);

        int row = kh ? rB : rA;
        float4 o = kh ? accB : accA;
        *(float4*)&g_ctx[((size_t)bh * L + q0 + row) * DK + dl] = o;
    }
}

// ---------------- output projection + residual (double-buffered) ------------
__global__ __launch_bounds__(256) void oproj_kernel(
    const float* __restrict__ X, const float* __restrict__ Wo)
{
    __shared__ float As[2][8][128];
    __shared__ float Bs[2][8][128];

    const int tid  = threadIdx.x;
    const int row0 = blockIdx.y * 128;
    const int col0 = blockIdx.x * 128;

    const int arow = tid >> 1, ac4 = (tid & 1) * 4;
    const int brow = tid >> 5, bc4 = (tid & 31) * 4;
    const int ty = tid >> 4, tx = tid & 15;

    float acc[8][8];
#pragma unroll
    for (int i = 0; i < 8; i++)
#pragma unroll
        for (int j = 0; j < 8; j++) acc[i][j] = 0.f;

    const int r_a = row0 + arow;
    const int ba_ = r_a >> 10, la_ = r_a & 1023;
    const float* Bptr = Wo + (size_t)brow * DM + col0 + bc4;

    auto loadA = [&](int k0) -> float4 {
        int c  = k0 + ac4;
        int h_ = c >> 6, d_ = c & 63;
        return *(const float4*)&g_ctx[(((size_t)(ba_ * H + h_)) * L + la_) * DK + d_];
    };

    {
        float4 av = loadA(0);
        float4 bv = *(const float4*)(Bptr);
        As[0][ac4 + 0][arow] = av.x;
        As[0][ac4 + 1][arow] = av.y;
        As[0][ac4 + 2][arow] = av.z;
        As[0][ac4 + 3][arow] = av.w;
        *(float4*)&Bs[0][brow][bc4] = bv;
    }
    __syncthreads();

    int buf = 0;
    for (int k0 = 0; k0 < DM; k0 += 8) {
        float4 av, bv;
        const bool nxt = (k0 + 8) < DM;
        if (nxt) {
            av = loadA(k0 + 8);
            bv = *(const float4*)(Bptr + (size_t)(k0 + 8) * DM);
        }
#pragma unroll
        for (int k = 0; k < 8; k++) {
            float4 a1 = *(const float4*)&As[buf][k][ty * 4];
            float4 a2 = *(const float4*)&As[buf][k][64 + ty * 4];
            float4 b1 = *(const float4*)&Bs[buf][k][tx * 4];
            float4 b2 = *(const float4*)&Bs[buf][k][64 + tx * 4];
            float a[8] = {a1.x, a1.y, a1.z, a1.w, a2.x, a2.y, a2.z, a2.w};
            float bb[8] = {b1.x, b1.y, b1.z, b1.w, b2.x, b2.y, b2.z, b2.w};
#pragma unroll
            for (int i = 0; i < 8; i++)
#pragma unroll
                for (int j = 0; j < 8; j++) acc[i][j] += a[i] * bb[j];
        }
        if (nxt) {
            As[buf ^ 1][ac4 + 0][arow] = av.x;
            As[buf ^ 1][ac4 + 1][arow] = av.y;
            As[buf ^ 1][ac4 + 2][arow] = av.z;
            As[buf ^ 1][ac4 + 3][arow] = av.w;
            *(float4*)&Bs[buf ^ 1][brow][bc4] = bv;
        }
        __syncthreads();
        buf ^= 1;
    }

#pragma unroll
    for (int i = 0; i < 8; i++) {
        int r = row0 + ((i < 4) ? (ty * 4 + i) : (64 + ty * 4 + (i - 4)));
#pragma unroll
        for (int g = 0; g < 2; g++) {
            int c0 = col0 + g * 64 + tx * 4;
            float4 xv = *(const float4*)&X[(size_t)r * DM + c0];
            float4 o;
            o.x = acc[i][g * 4 + 0] + xv.x;
            o.y = acc[i][g * 4 + 1] + xv.y;
            o.z = acc[i][g * 4 + 2] + xv.z;
            o.w = acc[i][g * 4 + 3] + xv.w;
            *(float4*)&g_preln[(size_t)r * DM + c0] = o;
        }
    }
}

// ---------------- layernorm -------------------------------------------------
__global__ __launch_bounds__(256) void ln_kernel(
    const float* __restrict__ gamma, const float* __restrict__ beta,
    float* __restrict__ out)
{
    __shared__ float red[18];
    const int r = blockIdx.x, tid = threadIdx.x;
    const float4* x4 = (const float4*)(g_preln + (size_t)r * DM);
    float4 v = x4[tid];

    float s = v.x + v.y + v.z + v.w;
#pragma unroll
    for (int off = 16; off; off >>= 1) s += __shfl_xor_sync(0xffffffffu, s, off);
    if ((tid & 31) == 0) red[tid >> 5] = s;
    __syncthreads();
    if (tid == 0) {
        float t = 0.f;
        for (int i = 0; i < 8; i++) t += red[i];
        red[16] = t * (1.f / 1024.f);
    }
    __syncthreads();
    float mean = red[16];

    float dx = v.x - mean, dy = v.y - mean, dz = v.z - mean, dw = v.w - mean;
    float ss = dx * dx + dy * dy + dz * dz + dw * dw;
#pragma unroll
    for (int off = 16; off; off >>= 1) ss += __shfl_xor_sync(0xffffffffu, ss, off);
    if ((tid & 31) == 0) red[8 + (tid >> 5)] = ss;
    __syncthreads();
    if (tid == 0) {
        float t = 0.f;
        for (int i = 0; i < 8; i++) t += red[8 + i];
        red[17] = rsqrtf(t * (1.f / 1024.f) + 1e-6f);
    }
    __syncthreads();
    float rs = red[17];

    float4 g = ((const float4*)gamma)[tid];
    float4 bb = ((const float4*)beta)[tid];
    float4 o;
    o.x = dx * rs * g.x + bb.x;
    o.y = dy * rs * g.y + bb.y;
    o.z = dz * rs * g.z + bb.z;
    o.w = dw * rs * g.w + bb.w;

    float* op = out ? (out + (size_t)r * DM) : (g_preln + (size_t)r * DM);
    ((float4*)op)[tid] = o;
}

// ---------------- launch -----------------------------------------------------
extern "C" void kernel_launch(void* const* d_in, const int* in_sizes, int n_in,
                              void* d_out, int out_size)
{
    const float* X     = (const float*)d_in[0];
    const void*  mask  = d_in[1];
    const float* Wq    = (const float*)d_in[2];
    const float* Wk    = (const float*)d_in[3];
    const float* Wv    = (const float*)d_in[4];
    const float* Wo    = (const float*)d_in[5];
    const float* gamma = (const float*)d_in[6];
    const float* beta  = (const float*)d_in[7];

    const long long LNN = (long long)B * L * DM;
    const long long ATT = (long long)BH * L * L;

    float* out_ln = nullptr;
    float* out_attn = nullptr;
    long long os = (long long)out_size;
    if (os >= LNN + ATT) {
        out_ln = (float*)d_out;
        out_attn = (float*)d_out + LNN;
    } else if (os == ATT) {
        out_attn = (float*)d_out;
    } else {
        out_ln = (float*)d_out;
    }

    detect_mask_kernel<<<1, 256>>>((const unsigned int*)mask);
    qkv_kernel<<<dim3(8, 64, 3), 256>>>(X, Wq, Wk, Wv);

    size_t smem = (size_t)(16 * SP + 2 * 64 * 68) * sizeof(float);
    cudaFuncSetAttribute(attn_kernel,
                         cudaFuncAttributeMaxDynamicSharedMemorySize, (int)smem);
    attn_kernel<<<dim3(L / 16, BH), 256, smem>>>(mask, out_attn);

    oproj_kernel<<<dim3(8, 64), 256>>>(X, Wo);
    ln_kernel<<<B * L, 256>>>(gamma, beta, out_ln);
}

// round 5
// speedup vs baseline: 2.0613x; 1.2312x over previous
#include <cuda_runtime.h>
#include <cuda_bf16.h>
#include <cstdint>
#include <cstddef>

#define B 8
#define L 1024
#define H 16
#define DK 64
#define DM 1024
#define BH (B*H)
#define SP 1028

// ---------------- scratch ----------------------------------------------------
__device__ float g_Q[(size_t)BH * L * DK];
__device__ float g_K[(size_t)BH * L * DK];
__device__ float g_V[(size_t)BH * L * DK];
__device__ float g_ctx[(size_t)BH * L * DK];
__device__ float g_preln[(size_t)B * L * DM];
__device__ int   g_mask_u8;

// bf16 split buffers
__device__ __nv_bfloat16 g_Xh[(size_t)B * L * DM];
__device__ __nv_bfloat16 g_Xl[(size_t)B * L * DM];
__device__ __nv_bfloat16 g_Wh[4][(size_t)DM * DM];   // q,k,v,o
__device__ __nv_bfloat16 g_Wl[4][(size_t)DM * DM];
__device__ __nv_bfloat16 g_Ch[(size_t)B * L * DM];   // ctx as 2D [8192][1024]
__device__ __nv_bfloat16 g_Cl[(size_t)B * L * DM];

__device__ __forceinline__ uint32_t smem_u32(const void* p) {
    return (uint32_t)__cvta_generic_to_shared(p);
}

// ---------------- mask dtype detection --------------------------------------
__global__ void detect_mask_kernel(const unsigned int* __restrict__ m)
{
    __shared__ int s_any;
    if (threadIdx.x == 0) s_any = 0;
    __syncthreads();
    int any = 0;
    for (int i = threadIdx.x; i < 16384; i += 256)
        if (m[i] > 1u) any = 1;
    if (any) atomicOr(&s_any, 1);
    __syncthreads();
    if (threadIdx.x == 0) g_mask_u8 = s_any;
}

// ---------------- fp32 -> bf16 hi/lo split ----------------------------------
__global__ __launch_bounds__(256) void cvt_split_kernel(
    const float4* __restrict__ in, __nv_bfloat16* __restrict__ h,
    __nv_bfloat16* __restrict__ l, int n4)
{
    int i = blockIdx.x * 256 + threadIdx.x;
    if (i >= n4) return;
    float4 v = in[i];
    __nv_bfloat16 h0 = __float2bfloat16(v.x);
    __nv_bfloat16 h1 = __float2bfloat16(v.y);
    __nv_bfloat16 h2 = __float2bfloat16(v.z);
    __nv_bfloat16 h3 = __float2bfloat16(v.w);
    __nv_bfloat162* hp = (__nv_bfloat162*)(h + (size_t)i * 4);
    hp[0] = __nv_bfloat162(h0, h1);
    hp[1] = __nv_bfloat162(h2, h3);
    __nv_bfloat162* lp = (__nv_bfloat162*)(l + (size_t)i * 4);
    lp[0] = __nv_bfloat162(__float2bfloat16(v.x - __bfloat162float(h0)),
                           __float2bfloat16(v.y - __bfloat162float(h1)));
    lp[1] = __nv_bfloat162(__float2bfloat16(v.z - __bfloat162float(h2)),
                           __float2bfloat16(v.w - __bfloat162float(h3)));
}

// ---------------- ctx [bh][l][64] -> 2D [8192][1024] bf16 split --------------
__global__ __launch_bounds__(256) void cvt_ctx_kernel()
{
    int i = blockIdx.x * 256 + threadIdx.x;            // float4 index, 2.1M
    if (i >= (B * L * DM) / 4) return;
    int r = i >> 8;                  // row 0..8191
    int c = (i & 255) * 4;           // col
    int b_ = r >> 10, l_ = r & 1023;
    int h_ = c >> 6, d_ = c & 63;
    float4 v = *(const float4*)&g_ctx[(((size_t)(b_ * H + h_)) * L + l_) * DK + d_];
    __nv_bfloat16 h0 = __float2bfloat16(v.x);
    __nv_bfloat16 h1 = __float2bfloat16(v.y);
    __nv_bfloat16 h2 = __float2bfloat16(v.z);
    __nv_bfloat16 h3 = __float2bfloat16(v.w);
    __nv_bfloat162* hp = (__nv_bfloat162*)(g_Ch + (size_t)r * DM + c);
    hp[0] = __nv_bfloat162(h0, h1);
    hp[1] = __nv_bfloat162(h2, h3);
    __nv_bfloat162* lp = (__nv_bfloat162*)(g_Cl + (size_t)r * DM + c);
    lp[0] = __nv_bfloat162(__float2bfloat16(v.x - __bfloat162float(h0)),
                           __float2bfloat16(v.y - __bfloat162float(h1)));
    lp[1] = __nv_bfloat162(__float2bfloat16(v.z - __bfloat162float(h2)),
                           __float2bfloat16(v.w - __bfloat162float(h3)));
}

// ---------------- mma.sync bf16 split GEMM core ------------------------------
// 128x128 tile, 256 thr, 8 warps (2x4), warp tile 64x32, m16n8k16.
// 96 k-chunks of 32: phase0 Ah*Bh, phase1 Al*Bh, phase2 Ah*Bl.

#define MMA_STEP(afr, bfr, accp)                                              \
    asm volatile(                                                              \
        "mma.sync.aligned.m16n8k16.row.col.f32.bf16.bf16.f32 "                 \
        "{%0,%1,%2,%3},{%4,%5,%6,%7},{%8,%9},{%0,%1,%2,%3};"                   \
        : "+f"((accp)[0]), "+f"((accp)[1]), "+f"((accp)[2]), "+f"((accp)[3])   \
        : "r"((afr)[0]), "r"((afr)[1]), "r"((afr)[2]), "r"((afr)[3]),          \
          "r"((bfr)[0]), "r"((bfr)[1]))

#define GEMM_MAIN(AH, AL, BH_, BL_)                                            \
    __shared__ __nv_bfloat16 sA[2][128][40];                                   \
    __shared__ __nv_bfloat16 sB[2][32][136];                                   \
    const int tid = threadIdx.x, lane = tid & 31, warp = tid >> 5;             \
    const int wm = warp >> 2, wn = warp & 3;                                   \
    const int row0 = blockIdx.y * 128, col0 = blockIdx.x * 128;                \
    float acc[4][4][4];                                                        \
    _Pragma("unroll") for (int i = 0; i < 4; i++)                              \
    _Pragma("unroll") for (int j = 0; j < 4; j++)                              \
    _Pragma("unroll") for (int f = 0; f < 4; f++) acc[i][j][f] = 0.f;          \
    const int ar = tid >> 1, ac = (tid & 1) * 16;                              \
    const int br = tid >> 3, bc = (tid & 7) * 8;                               \
    {                                                                          \
        uint4 a0 = *(const uint4*)(AH + (size_t)(row0 + ar) * DM + ac);        \
        uint4 a1 = *(const uint4*)(AH + (size_t)(row0 + ar) * DM + ac + 8);    \
        uint4 b0 = *(const uint4*)(BH_ + (size_t)br * DM + col0 + bc);         \
        uint4 b1 = *(const uint4*)(BH_ + (size_t)br * DM + col0 + bc + 64);    \
        *(uint4*)&sA[0][ar][ac] = a0;  *(uint4*)&sA[0][ar][ac + 8] = a1;       \
        *(uint4*)&sB[0][br][bc] = b0;  *(uint4*)&sB[0][br][bc + 64] = b1;      \
    }                                                                          \
    __syncthreads();                                                           \
    int buf = 0;                                                               \
    for (int cc = 0; cc < 96; cc++) {                                          \
        uint4 a0, a1, b0, b1;                                                  \
        const bool nxt = (cc + 1) < 96;                                        \
        if (nxt) {                                                             \
            int ph = (cc + 1) >> 5, k0 = ((cc + 1) & 31) * 32;                 \
            const __nv_bfloat16* Ap = (ph == 1) ? AL : AH;                     \
            const __nv_bfloat16* Bp = (ph == 2) ? BL_ : BH_;                   \
            a0 = *(const uint4*)(Ap + (size_t)(row0 + ar) * DM + k0 + ac);     \
            a1 = *(const uint4*)(Ap + (size_t)(row0 + ar) * DM + k0 + ac + 8); \
            b0 = *(const uint4*)(Bp + (size_t)(k0 + br) * DM + col0 + bc);     \
            b1 = *(const uint4*)(Bp + (size_t)(k0 + br) * DM + col0 + bc + 64);\
        }                                                                      \
        _Pragma("unroll")                                                      \
        for (int ks = 0; ks < 32; ks += 16) {                                  \
            uint32_t afr[4][4], bfr[4][2];                                     \
            _Pragma("unroll")                                                  \
            for (int i = 0; i < 4; i++) {                                      \
                uint32_t ad = smem_u32(                                        \
                    &sA[buf][wm * 64 + i * 16 + (lane & 15)]                   \
                        [ks + (lane >> 4) * 8]);                               \
                asm volatile(                                                  \
                    "ldmatrix.sync.aligned.m8n8.x4.shared.b16 "                \
                    "{%0,%1,%2,%3},[%4];"                                      \
                    : "=r"(afr[i][0]), "=r"(afr[i][1]),                        \
                      "=r"(afr[i][2]), "=r"(afr[i][3]) : "r"(ad));             \
            }                                                                  \
            _Pragma("unroll")                                                  \
            for (int j = 0; j < 4; j++) {                                      \
                uint32_t bd = smem_u32(                                        \
                    &sB[buf][ks + (lane & 15)][wn * 32 + j * 8]);              \
                asm volatile(                                                  \
                    "ldmatrix.sync.aligned.m8n8.x2.trans.shared.b16 "          \
                    "{%0,%1},[%2];"                                            \
                    : "=r"(bfr[j][0]), "=r"(bfr[j][1]) : "r"(bd));             \
            }                                                                  \
            _Pragma("unroll")                                                  \
            for (int i = 0; i < 4; i++)                                        \
            _Pragma("unroll")                                                  \
            for (int j = 0; j < 4; j++) MMA_STEP(afr[i], bfr[j], acc[i][j]);   \
        }                                                                      \
        if (nxt) {                                                             \
            *(uint4*)&sA[buf ^ 1][ar][ac] = a0;                                \
            *(uint4*)&sA[buf ^ 1][ar][ac + 8] = a1;                            \
            *(uint4*)&sB[buf ^ 1][br][bc] = b0;                                \
            *(uint4*)&sB[buf ^ 1][br][bc + 64] = b1;                           \
        }                                                                      \
        __syncthreads();                                                       \
        buf ^= 1;                                                              \
    }

__global__ __launch_bounds__(256) void qkv_mma_kernel()
{
    const __nv_bfloat16* AH = g_Xh;
    const __nv_bfloat16* AL = g_Xl;
    const __nv_bfloat16* BHp = g_Wh[blockIdx.z];
    const __nv_bfloat16* BLp = g_Wl[blockIdx.z];
    float* Out = (blockIdx.z == 0) ? g_Q : (blockIdx.z == 1) ? g_K : g_V;

    GEMM_MAIN(AH, AL, BHp, BLp)

    const int lr = lane >> 2, lc = (lane & 3) * 2;
#pragma unroll
    for (int i = 0; i < 4; i++) {
        int r0 = row0 + wm * 64 + i * 16 + lr;
#pragma unroll
        for (int j = 0; j < 4; j++) {
            int c = col0 + wn * 32 + j * 8 + lc;
            int h_ = c >> 6, d_ = c & 63;
#pragma unroll
            for (int hrow = 0; hrow < 2; hrow++) {
                int r = r0 + hrow * 8;
                int b_ = r >> 10, l_ = r & 1023;
                float2 o;
                o.x = acc[i][j][hrow * 2 + 0];
                o.y = acc[i][j][hrow * 2 + 1];
                *(float2*)&Out[(((size_t)(b_ * H + h_)) * L + l_) * DK + d_] = o;
            }
        }
    }
}

__global__ __launch_bounds__(256) void oproj_mma_kernel(const float* __restrict__ X)
{
    const __nv_bfloat16* AH = g_Ch;
    const __nv_bfloat16* AL = g_Cl;
    const __nv_bfloat16* BHp = g_Wh[3];
    const __nv_bfloat16* BLp = g_Wl[3];

    GEMM_MAIN(AH, AL, BHp, BLp)

    const int lr = lane >> 2, lc = (lane & 3) * 2;
#pragma unroll
    for (int i = 0; i < 4; i++) {
        int r0 = row0 + wm * 64 + i * 16 + lr;
#pragma unroll
        for (int j = 0; j < 4; j++) {
            int c = col0 + wn * 32 + j * 8 + lc;
#pragma unroll
            for (int hrow = 0; hrow < 2; hrow++) {
                int r = r0 + hrow * 8;
                float2 xv = *(const float2*)&X[(size_t)r * DM + c];
                float2 o;
                o.x = acc[i][j][hrow * 2 + 0] + xv.x;
                o.y = acc[i][j][hrow * 2 + 1] + xv.y;
                *(float2*)&g_preln[(size_t)r * DM + c] = o;
            }
        }
    }
}

// ---------------- fused attention (unchanged from R4) ------------------------
__global__ __launch_bounds__(256, 2) void attn_kernel(
    const void* __restrict__ mask, float* __restrict__ attn_out)
{
    extern __shared__ float sm[];
    float* S  = sm;
    float* KV = sm + 16 * SP;

    const int tid = threadIdx.x;
    const int bh  = blockIdx.y;
    const int b_  = bh >> 4;
    const int q0  = blockIdx.x * 16;
    const int u8  = g_mask_u8;

    const float* Qp = g_Q + (size_t)bh * L * DK;
    const float* Kp = g_K + (size_t)bh * L * DK;
    const float* Vp = g_V + (size_t)bh * L * DK;

    const int r2 = tid >> 5;
    const int dh = (tid >> 4) & 1;
    const int kl = tid & 15;
    const int rA = 2 * r2, rB = 2 * r2 + 1;

    const int li_r[4] = { (tid + 0) >> 4, (tid + 256) >> 4,
                          (tid + 512) >> 4, (tid + 768) >> 4 };
    const int li_d = (tid & 15) * 4;

    float4 qa[8], qb[8];
#pragma unroll
    for (int i = 0; i < 8; i++) {
        qa[i] = *(const float4*)(Qp + (size_t)(q0 + rA) * DK + dh * 32 + i * 4);
        qb[i] = *(const float4*)(Qp + (size_t)(q0 + rB) * DK + dh * 32 + i * 4);
    }

    {
#pragma unroll
        for (int t = 0; t < 4; t++) {
            float4 v = *(const float4*)(Kp + (size_t)li_r[t] * DK + li_d);
            *(float4*)&KV[li_r[t] * 68 + li_d] = v;
        }
        __syncthreads();
        int buf = 0;
        for (int kc = 0; kc < L; kc += 64) {
            float4 pre[4];
            const bool nxt = (kc + 64) < L;
            if (nxt) {
#pragma unroll
                for (int t = 0; t < 4; t++)
                    pre[t] = *(const float4*)(Kp + (size_t)(kc + 64 + li_r[t]) * DK + li_d);
            }
            const float* KB = KV + buf * (64 * 68);
#pragma unroll
            for (int e = 0; e < 4; e++) {
                int key = e * 16 + kl;
                const float4* kp = (const float4*)&KB[key * 68 + dh * 32];
                float sa = 0.f, sb = 0.f;
#pragma unroll
                for (int i = 0; i < 8; i++) {
                    float4 k4 = kp[i];
                    sa += qa[i].x * k4.x + qa[i].y * k4.y + qa[i].z * k4.z + qa[i].w * k4.w;
                    sb += qb[i].x * k4.x + qb[i].y * k4.y + qb[i].z * k4.z + qb[i].w * k4.w;
                }
                sa += __shfl_xor_sync(0xffffffffu, sa, 16);
                sb += __shfl_xor_sync(0xffffffffu, sb, 16);
                int row = dh ? rB : rA;
                float sv = dh ? sb : sa;
                int gk = kc + key;
                size_t midx = ((size_t)b_ * L + q0 + row) * L + gk;
                bool msk = u8 ? (((const unsigned char*)mask)[midx] != 0)
                              : (((const int*)mask)[midx] != 0);
                S[row * SP + gk] = msk ? -1e9f : sv * 0.125f;
            }
            if (nxt) {
                float* KN = KV + (buf ^ 1) * (64 * 68);
#pragma unroll
                for (int t = 0; t < 4; t++)
                    *(float4*)&KN[li_r[t] * 68 + li_d] = pre[t];
            }
            __syncthreads();
            buf ^= 1;
        }
    }

    {
        const int row = tid >> 4;
        const int c0  = tid & 15;
        float mx = -3.4e38f;
        for (int k = 0; k < 64; k++) mx = fmaxf(mx, S[row * SP + c0 + 16 * k]);
#pragma unroll
        for (int off = 8; off; off >>= 1)
            mx = fmaxf(mx, __shfl_xor_sync(0xffffffffu, mx, off));
        float sum = 0.f;
        for (int k = 0; k < 64; k++) {
            int c = c0 + 16 * k;
            float e_ = __expf(S[row * SP + c] - mx);
            S[row * SP + c] = e_;
            sum += e_;
        }
#pragma unroll
        for (int off = 8; off; off >>= 1)
            sum += __shfl_xor_sync(0xffffffffu, sum, off);
        float inv = 1.f / sum;
        for (int k = 0; k < 64; k++) S[row * SP + c0 + 16 * k] *= inv;
    }
    __syncthreads();

    if (attn_out) {
        for (int idx = tid; idx < 16 * L; idx += 256) {
            int r = idx >> 10, c = idx & 1023;
            attn_out[((size_t)bh * L + q0 + r) * L + c] = S[r * SP + c];
        }
    }

    {
        const int kh = (tid >> 4) & 1;
        const int dl = (tid & 15) * 4;
        float4 accA = make_float4(0.f, 0.f, 0.f, 0.f);
        float4 accB = make_float4(0.f, 0.f, 0.f, 0.f);

#pragma unroll
        for (int t = 0; t < 4; t++) {
            float4 v = *(const float4*)(Vp + (size_t)li_r[t] * DK + li_d);
            *(float4*)&KV[li_r[t] * 68 + li_d] = v;
        }
        __syncthreads();
        int buf = 0;
        for (int kc = 0; kc < L; kc += 64) {
            float4 pre[4];
            const bool nxt = (kc + 64) < L;
            if (nxt) {
#pragma unroll
                for (int t = 0; t < 4; t++)
                    pre[t] = *(const float4*)(Vp + (size_t)(kc + 64 + li_r[t]) * DK + li_d);
            }
            const float* VB = KV + buf * (64 * 68);
#pragma unroll
            for (int g = 0; g < 8; g++) {
                int k0 = kh * 32 + g * 4;
                float4 pA = *(const float4*)&S[rA * SP + kc + k0];
                float4 pB = *(const float4*)&S[rB * SP + kc + k0];
                float4 v0 = *(const float4*)&VB[(k0 + 0) * 68 + dl];
                float4 v1 = *(const float4*)&VB[(k0 + 1) * 68 + dl];
                float4 v2 = *(const float4*)&VB[(k0 + 2) * 68 + dl];
                float4 v3 = *(const float4*)&VB[(k0 + 3) * 68 + dl];
                accA.x += pA.x * v0.x + pA.y * v1.x + pA.z * v2.x + pA.w * v3.x;
                accA.y += pA.x * v0.y + pA.y * v1.y + pA.z * v2.y + pA.w * v3.y;
                accA.z += pA.x * v0.z + pA.y * v1.z + pA.z * v2.z + pA.w * v3.z;
                accA.w += pA.x * v0.w + pA.y * v1.w + pA.z * v2.w + pA.w * v3.w;
                accB.x += pB.x * v0.x + pB.y * v1.x + pB.z * v2.x + pB.w * v3.x;
                accB.y += pB.x * v0.y + pB.y * v1.y + pB.z * v2.y + pB.w * v3.y;
                accB.z += pB.x * v0.z + pB.y * v1.z + pB.z * v2.z + pB.w * v3.z;
                accB.w += pB.x * v0.w + pB.y * v1.w + pB.z * v2.w + pB.w * v3.w;
            }
            if (nxt) {
                float* VN = KV + (buf ^ 1) * (64 * 68);
#pragma unroll
                for (int t = 0; t < 4; t++)
                    *(float4*)&VN[li_r[t] * 68 + li_d] = pre[t];
            }
            __syncthreads();
            buf ^= 1;
        }

        accA.x += __shfl_xor_sync(0xffffffffu, accA.x, 16);
        accA.y += __shfl_xor_sync(0xffffffffu, accA.y, 16);
        accA.z += __shfl_xor_sync(0xffffffffu, accA.z, 16);
        accA.w += __shfl_xor_sync(0xffffffffu, accA.w, 16);
        accB.x += __shfl_xor_sync(0xffffffffu, accB.x, 16);
        accB.y += __shfl_xor_sync(0xffffffffu, accB.y, 16);
        accB.z += __shfl_xor_sync(0xffffffffu, accB.z, 16);
        accB.w += __shfl_xor_sync(0xffffffffu, accB.w, 16);

        int row = kh ? rB : rA;
        float4 o = kh ? accB : accA;
        *(float4*)&g_ctx[((size_t)bh * L + q0 + row) * DK + dl] = o;
    }
}

// ---------------- layernorm --------------------------------------------------
__global__ __launch_bounds__(256) void ln_kernel(
    const float* __restrict__ gamma, const float* __restrict__ beta,
    float* __restrict__ out)
{
    __shared__ float red[18];
    const int r = blockIdx.x, tid = threadIdx.x;
    const float4* x4 = (const float4*)(g_preln + (size_t)r * DM);
    float4 v = x4[tid];

    float s = v.x + v.y + v.z + v.w;
#pragma unroll
    for (int off = 16; off; off >>= 1) s += __shfl_xor_sync(0xffffffffu, s, off);
    if ((tid & 31) == 0) red[tid >> 5] = s;
    __syncthreads();
    if (tid == 0) {
        float t = 0.f;
        for (int i = 0; i < 8; i++) t += red[i];
        red[16] = t * (1.f / 1024.f);
    }
    __syncthreads();
    float mean = red[16];

    float dx = v.x - mean, dy = v.y - mean, dz = v.z - mean, dw = v.w - mean;
    float ss = dx * dx + dy * dy + dz * dz + dw * dw;
#pragma unroll
    for (int off = 16; off; off >>= 1) ss += __shfl_xor_sync(0xffffffffu, ss, off);
    if ((tid & 31) == 0) red[8 + (tid >> 5)] = ss;
    __syncthreads();
    if (tid == 0) {
        float t = 0.f;
        for (int i = 0; i < 8; i++) t += red[8 + i];
        red[17] = rsqrtf(t * (1.f / 1024.f) + 1e-6f);
    }
    __syncthreads();
    float rs = red[17];

    float4 g = ((const float4*)gamma)[tid];
    float4 bb = ((const float4*)beta)[tid];
    float4 o;
    o.x = dx * rs * g.x + bb.x;
    o.y = dy * rs * g.y + bb.y;
    o.z = dz * rs * g.z + bb.z;
    o.w = dw * rs * g.w + bb.w;

    float* op = out ? (out + (size_t)r * DM) : (g_preln + (size_t)r * DM);
    ((float4*)op)[tid] = o;
}

// ---------------- launch -----------------------------------------------------
extern "C" void kernel_launch(void* const* d_in, const int* in_sizes, int n_in,
                              void* d_out, int out_size)
{
    const float* X     = (const float*)d_in[0];
    const void*  mask  = d_in[1];
    const float* Wq    = (const float*)d_in[2];
    const float* Wk    = (const float*)d_in[3];
    const float* Wv    = (const float*)d_in[4];
    const float* Wo    = (const float*)d_in[5];
    const float* gamma = (const float*)d_in[6];
    const float* beta  = (const float*)d_in[7];

    const long long LNN = (long long)B * L * DM;
    const long long ATT = (long long)BH * L * L;

    float* out_ln = nullptr;
    float* out_attn = nullptr;
    long long os = (long long)out_size;
    if (os >= LNN + ATT) {
        out_ln = (float*)d_out;
        out_attn = (float*)d_out + LNN;
    } else if (os == ATT) {
        out_attn = (float*)d_out;
    } else {
        out_ln = (float*)d_out;
    }

    detect_mask_kernel<<<1, 256>>>((const unsigned int*)mask);

    // bf16 hi/lo splits
    __nv_bfloat16 *Xh, *Xl, *Wh0, *Wl0;
    cudaGetSymbolAddress((void**)&Xh, g_Xh);
    cudaGetSymbolAddress((void**)&Xl, g_Xl);
    cudaGetSymbolAddress((void**)&Wh0, g_Wh);
    cudaGetSymbolAddress((void**)&Wl0, g_Wl);

    int nX4 = (B * L * DM) / 4;          // 2,097,152
    int nW4 = (DM * DM) / 4;             // 262,144
    cvt_split_kernel<<<(nX4 + 255) / 256, 256>>>((const float4*)X, Xh, Xl, nX4);
    cvt_split_kernel<<<(nW4 + 255) / 256, 256>>>((const float4*)Wq,
        Wh0 + 0 * (size_t)DM * DM, Wl0 + 0 * (size_t)DM * DM, nW4);
    cvt_split_kernel<<<(nW4 + 255) / 256, 256>>>((const float4*)Wk,
        Wh0 + 1 * (size_t)DM * DM, Wl0 + 1 * (size_t)DM * DM, nW4);
    cvt_split_kernel<<<(nW4 + 255) / 256, 256>>>((const float4*)Wv,
        Wh0 + 2 * (size_t)DM * DM, Wl0 + 2 * (size_t)DM * DM, nW4);
    cvt_split_kernel<<<(nW4 + 255) / 256, 256>>>((const float4*)Wo,
        Wh0 + 3 * (size_t)DM * DM, Wl0 + 3 * (size_t)DM * DM, nW4);

    qkv_mma_kernel<<<dim3(8, 64, 3), 256>>>();

    size_t smem = (size_t)(16 * SP + 2 * 64 * 68) * sizeof(float);
    cudaFuncSetAttribute(attn_kernel,
                         cudaFuncAttributeMaxDynamicSharedMemorySize, (int)smem);
    attn_kernel<<<dim3(L / 16, BH), 256, smem>>>(mask, out_attn);

    cvt_ctx_kernel<<<(nX4 + 255) / 256, 256>>>();
    oproj_mma_kernel<<<dim3(8, 64), 256>>>(X);
    ln_kernel<<<B * L, 256>>>(gamma, beta, out_ln);
}

// round 7
// speedup vs baseline: 2.4437x; 1.1855x over previous
#include <cuda_runtime.h>
#include <cuda_bf16.h>
#include <cstdint>
#include <cstddef>

#define B 8
#define L 1024
#define H 16
#define DK 64
#define DM 1024
#define BH (B*H)

// ---------------- scratch ----------------------------------------------------
__device__ float g_preln[(size_t)B * L * DM];
__device__ int   g_mask_u8;

// bf16 split buffers
__device__ __nv_bfloat16 g_Xh[(size_t)B * L * DM];
__device__ __nv_bfloat16 g_Xl[(size_t)B * L * DM];
__device__ __nv_bfloat16 g_Wh[4][(size_t)DM * DM];   // q,k,v,o
__device__ __nv_bfloat16 g_Wl[4][(size_t)DM * DM];
__device__ __nv_bfloat16 g_Qh[(size_t)BH * L * DK];  // pre-scaled by 0.125
__device__ __nv_bfloat16 g_Ql[(size_t)BH * L * DK];
__device__ __nv_bfloat16 g_Kh[(size_t)BH * L * DK];
__device__ __nv_bfloat16 g_Kl[(size_t)BH * L * DK];
__device__ __nv_bfloat16 g_Vh[(size_t)BH * L * DK];
__device__ __nv_bfloat16 g_Vl[(size_t)BH * L * DK];
__device__ __nv_bfloat16 g_Ch[(size_t)B * L * DM];   // ctx 2D [8192][1024]
__device__ __nv_bfloat16 g_Cl[(size_t)B * L * DM];

__device__ __forceinline__ uint32_t smem_u32(const void* p) {
    return (uint32_t)__cvta_generic_to_shared(p);
}

#define MMA_STEP(afr, bfr, accp)                                              \
    asm volatile(                                                              \
        "mma.sync.aligned.m16n8k16.row.col.f32.bf16.bf16.f32 "                 \
        "{%0,%1,%2,%3},{%4,%5,%6,%7},{%8,%9},{%0,%1,%2,%3};"                   \
        : "+f"((accp)[0]), "+f"((accp)[1]), "+f"((accp)[2]), "+f"((accp)[3])   \
        : "r"((afr)[0]), "r"((afr)[1]), "r"((afr)[2]), "r"((afr)[3]),          \
          "r"((bfr)[0]), "r"((bfr)[1]))

#define LDSM_X4(frag, ad)                                                      \
    asm volatile("ldmatrix.sync.aligned.m8n8.x4.shared.b16 {%0,%1,%2,%3},[%4];"\
        : "=r"((frag)[0]), "=r"((frag)[1]), "=r"((frag)[2]), "=r"((frag)[3])   \
        : "r"(ad))

#define LDSM_X2(frag, ad)                                                      \
    asm volatile("ldmatrix.sync.aligned.m8n8.x2.shared.b16 {%0,%1},[%2];"      \
        : "=r"((frag)[0]), "=r"((frag)[1]) : "r"(ad))

#define LDSM_X2T(frag, ad)                                                     \
    asm volatile("ldmatrix.sync.aligned.m8n8.x2.trans.shared.b16 {%0,%1},[%2];"\
        : "=r"((frag)[0]), "=r"((frag)[1]) : "r"(ad))

// ---------------- mask dtype detection --------------------------------------
__global__ void detect_mask_kernel(const unsigned int* __restrict__ m)
{
    __shared__ int s_any;
    if (threadIdx.x == 0) s_any = 0;
    __syncthreads();
    int any = 0;
    for (int i = threadIdx.x; i < 16384; i += 256)
        if (m[i] > 1u) any = 1;
    if (any) atomicOr(&s_any, 1);
    __syncthreads();
    if (threadIdx.x == 0) g_mask_u8 = s_any;
}

// ---------------- fp32 -> bf16 hi/lo split ----------------------------------
__global__ __launch_bounds__(256) void cvt_split_kernel(
    const float4* __restrict__ in, __nv_bfloat16* __restrict__ h,
    __nv_bfloat16* __restrict__ l, int n4)
{
    int i = blockIdx.x * 256 + threadIdx.x;
    if (i >= n4) return;
    float4 v = in[i];
    __nv_bfloat16 h0 = __float2bfloat16(v.x);
    __nv_bfloat16 h1 = __float2bfloat16(v.y);
    __nv_bfloat16 h2 = __float2bfloat16(v.z);
    __nv_bfloat16 h3 = __float2bfloat16(v.w);
    __nv_bfloat162* hp = (__nv_bfloat162*)(h + (size_t)i * 4);
    hp[0] = __nv_bfloat162(h0, h1);
    hp[1] = __nv_bfloat162(h2, h3);
    __nv_bfloat162* lp = (__nv_bfloat162*)(l + (size_t)i * 4);
    lp[0] = __nv_bfloat162(__float2bfloat16(v.x - __bfloat162float(h0)),
                           __float2bfloat16(v.y - __bfloat162float(h1)));
    lp[1] = __nv_bfloat162(__float2bfloat16(v.z - __bfloat162float(h2)),
                           __float2bfloat16(v.w - __bfloat162float(h3)));
}

// ---------------- mma.sync bf16 split GEMM core ------------------------------
#define GEMM_MAIN(AH, AL, BH_, BL_)                                            \
    __shared__ __nv_bfloat16 sA[2][128][40];                                   \
    __shared__ __nv_bfloat16 sB[2][32][136];                                   \
    const int tid = threadIdx.x, lane = tid & 31, warp = tid >> 5;             \
    const int wm = warp >> 2, wn = warp & 3;                                   \
    const int row0 = blockIdx.y * 128, col0 = blockIdx.x * 128;                \
    float acc[4][4][4];                                                        \
    _Pragma("unroll") for (int i = 0; i < 4; i++)                              \
    _Pragma("unroll") for (int j = 0; j < 4; j++)                              \
    _Pragma("unroll") for (int f = 0; f < 4; f++) acc[i][j][f] = 0.f;          \
    const int ar = tid >> 1, ac = (tid & 1) * 16;                              \
    const int br = tid >> 3, bc = (tid & 7) * 8;                               \
    {                                                                          \
        uint4 a0 = *(const uint4*)(AH + (size_t)(row0 + ar) * DM + ac);        \
        uint4 a1 = *(const uint4*)(AH + (size_t)(row0 + ar) * DM + ac + 8);    \
        uint4 b0 = *(const uint4*)(BH_ + (size_t)br * DM + col0 + bc);         \
        uint4 b1 = *(const uint4*)(BH_ + (size_t)br * DM + col0 + bc + 64);    \
        *(uint4*)&sA[0][ar][ac] = a0;  *(uint4*)&sA[0][ar][ac + 8] = a1;       \
        *(uint4*)&sB[0][br][bc] = b0;  *(uint4*)&sB[0][br][bc + 64] = b1;      \
    }                                                                          \
    __syncthreads();                                                           \
    int buf = 0;                                                               \
    for (int cc = 0; cc < 96; cc++) {                                          \
        uint4 a0, a1, b0, b1;                                                  \
        const bool nxt = (cc + 1) < 96;                                        \
        if (nxt) {                                                             \
            int ph = (cc + 1) >> 5, k0 = ((cc + 1) & 31) * 32;                 \
            const __nv_bfloat16* Ap = (ph == 1) ? AL : AH;                     \
            const __nv_bfloat16* Bp = (ph == 2) ? BL_ : BH_;                   \
            a0 = *(const uint4*)(Ap + (size_t)(row0 + ar) * DM + k0 + ac);     \
            a1 = *(const uint4*)(Ap + (size_t)(row0 + ar) * DM + k0 + ac + 8); \
            b0 = *(const uint4*)(Bp + (size_t)(k0 + br) * DM + col0 + bc);     \
            b1 = *(const uint4*)(Bp + (size_t)(k0 + br) * DM + col0 + bc + 64);\
        }                                                                      \
        _Pragma("unroll")                                                      \
        for (int ks = 0; ks < 32; ks += 16) {                                  \
            uint32_t afr[4][4], bfr[4][2];                                     \
            _Pragma("unroll")                                                  \
            for (int i = 0; i < 4; i++) {                                      \
                uint32_t ad = smem_u32(                                        \
                    &sA[buf][wm * 64 + i * 16 + (lane & 15)]                   \
                        [ks + (lane >> 4) * 8]);                               \
                LDSM_X4(afr[i], ad);                                           \
            }                                                                  \
            _Pragma("unroll")                                                  \
            for (int j = 0; j < 4; j++) {                                      \
                uint32_t bd = smem_u32(                                        \
                    &sB[buf][ks + (lane & 15)][wn * 32 + j * 8]);              \
                LDSM_X2T(bfr[j], bd);                                          \
            }                                                                  \
            _Pragma("unroll")                                                  \
            for (int i = 0; i < 4; i++)                                        \
            _Pragma("unroll")                                                  \
            for (int j = 0; j < 4; j++) MMA_STEP(afr[i], bfr[j], acc[i][j]);   \
        }                                                                      \
        if (nxt) {                                                             \
            *(uint4*)&sA[buf ^ 1][ar][ac] = a0;                                \
            *(uint4*)&sA[buf ^ 1][ar][ac + 8] = a1;                            \
            *(uint4*)&sB[buf ^ 1][br][bc] = b0;                                \
            *(uint4*)&sB[buf ^ 1][br][bc + 64] = b1;                           \
        }                                                                      \
        __syncthreads();                                                       \
        buf ^= 1;                                                              \
    }

// QKV: writes bf16 hi/lo splits directly (Q pre-scaled by 0.125)
__global__ __launch_bounds__(256) void qkv_mma_kernel()
{
    const int z = blockIdx.z;
    const __nv_bfloat16* BHp = g_Wh[z];
    const __nv_bfloat16* BLp = g_Wl[z];

    GEMM_MAIN(g_Xh, g_Xl, BHp, BLp)

    __nv_bfloat16* Oh = (z == 0) ? g_Qh : (z == 1) ? g_Kh : g_Vh;
    __nv_bfloat16* Ol = (z == 0) ? g_Ql : (z == 1) ? g_Kl : g_Vl;
    const float sc = (z == 0) ? 0.125f : 1.0f;

    const int lr = lane >> 2, lc = (lane & 3) * 2;
#pragma unroll
    for (int i = 0; i < 4; i++) {
        int r0 = row0 + wm * 64 + i * 16 + lr;
#pragma unroll
        for (int j = 0; j < 4; j++) {
            int c = col0 + wn * 32 + j * 8 + lc;
            int h_ = c >> 6, d_ = c & 63;
#pragma unroll
            for (int hrow = 0; hrow < 2; hrow++) {
                int r = r0 + hrow * 8;
                int b_ = r >> 10, l_ = r & 1023;
                float v0 = acc[i][j][hrow * 2 + 0] * sc;
                float v1 = acc[i][j][hrow * 2 + 1] * sc;
                __nv_bfloat16 h0 = __float2bfloat16(v0);
                __nv_bfloat16 h1 = __float2bfloat16(v1);
                size_t off = (((size_t)(b_ * H + h_)) * L + l_) * DK + d_;
                *(__nv_bfloat162*)(Oh + off) = __nv_bfloat162(h0, h1);
                *(__nv_bfloat162*)(Ol + off) = __nv_bfloat162(
                    __float2bfloat16(v0 - __bfloat162float(h0)),
                    __float2bfloat16(v1 - __bfloat162float(h1)));
            }
        }
    }
}

__global__ __launch_bounds__(256) void oproj_mma_kernel(const float* __restrict__ X)
{
    GEMM_MAIN(g_Ch, g_Cl, g_Wh[3], g_Wl[3])

    const int lr = lane >> 2, lc = (lane & 3) * 2;
#pragma unroll
    for (int i = 0; i < 4; i++) {
        int r0 = row0 + wm * 64 + i * 16 + lr;
#pragma unroll
        for (int j = 0; j < 4; j++) {
            int c = col0 + wn * 32 + j * 8 + lc;
#pragma unroll
            for (int hrow = 0; hrow < 2; hrow++) {
                int r = r0 + hrow * 8;
                float2 xv = *(const float2*)&X[(size_t)r * DM + c];
                float2 o;
                o.x = acc[i][j][hrow * 2 + 0] + xv.x;
                o.y = acc[i][j][hrow * 2 + 1] + xv.y;
                *(float2*)&g_preln[(size_t)r * DM + c] = o;
            }
        }
    }
}

// ---------------- tensor-core attention --------------------------------------
// Block = (bh, 32 query rows), 256 thr / 8 warps (wm 2 x wn 4).
// smem (compacted): S[32][1028] f32 | Q hi/lo [32][72] | K/V hi/lo [128][72]
//                   | P hi/lo [32][136]
#define SOFF_Q  131584
#define SOFF_K  140800
#define SOFF_P  177664
#define ATTN_SMEM 195072

__global__ __launch_bounds__(256) void attn_mma_kernel(
    const void* __restrict__ mask, float* __restrict__ attn_out)
{
    extern __shared__ char smx[];
    float* S = (float*)smx;
    __nv_bfloat16* Qsh = (__nv_bfloat16*)(smx + SOFF_Q);
    __nv_bfloat16* Qsl = Qsh + 32 * 72;
    __nv_bfloat16* KVh = (__nv_bfloat16*)(smx + SOFF_K);
    __nv_bfloat16* KVl = KVh + 128 * 72;
    __nv_bfloat16* Ph  = (__nv_bfloat16*)(smx + SOFF_P);
    __nv_bfloat16* Pl  = Ph + 32 * 136;

    const int tid = threadIdx.x, lane = tid & 31, warp = tid >> 5;
    const int wm = warp >> 2, wn = warp & 3;
    const int bh = blockIdx.y, b_ = bh >> 4, q0 = blockIdx.x * 32;
    const int u8 = g_mask_u8;

    // ---- Q smem fill: 32 rows x 64, hi/lo ----
    {
        int r = tid >> 3, d0 = (tid & 7) * 8;
        *(uint4*)(Qsh + r * 72 + d0) =
            *(const uint4*)(g_Qh + ((size_t)bh * L + q0 + r) * DK + d0);
        *(uint4*)(Qsl + r * 72 + d0) =
            *(const uint4*)(g_Ql + ((size_t)bh * L + q0 + r) * DK + d0);
    }
    __syncthreads();

    // ---- Q fragments (held whole score phase) ----
    uint32_t qfh[4][4], qfl[4][4];
#pragma unroll
    for (int kk = 0; kk < 4; kk++) {
        uint32_t ad = smem_u32(Qsh + (wm * 16 + (lane & 15)) * 72 +
                               kk * 16 + (lane >> 4) * 8);
        LDSM_X4(qfh[kk], ad);
        ad = smem_u32(Qsl + (wm * 16 + (lane & 15)) * 72 +
                      kk * 16 + (lane >> 4) * 8);
        LDSM_X4(qfl[kk], ad);
    }

    // ---- score phase: 8 chunks of 128 keys ----
    for (int kc = 0; kc < L; kc += 128) {
        __syncthreads();
        {
            int r = tid >> 1, d0 = (tid & 1) * 32;
            const uint4* sh = (const uint4*)(g_Kh + ((size_t)bh * L + kc + r) * DK + d0);
            const uint4* sl = (const uint4*)(g_Kl + ((size_t)bh * L + kc + r) * DK + d0);
            uint4* dh = (uint4*)(KVh + r * 72 + d0);
            uint4* dl = (uint4*)(KVl + r * 72 + d0);
#pragma unroll
            for (int i = 0; i < 4; i++) { dh[i] = sh[i]; dl[i] = sl[i]; }
        }
        __syncthreads();

        float acc[4][4];
#pragma unroll
        for (int t = 0; t < 4; t++)
#pragma unroll
            for (int f = 0; f < 4; f++) acc[t][f] = 0.f;

#pragma unroll
        for (int kk = 0; kk < 4; kk++) {
            uint32_t bfh[4][2], bfl[4][2];
#pragma unroll
            for (int t = 0; t < 4; t++) {
                int kb = wn * 32 + t * 8;
                uint32_t ad = smem_u32(KVh + (kb + (lane & 7)) * 72 +
                                       kk * 16 + ((lane >> 3) & 1) * 8);
                LDSM_X2(bfh[t], ad);
                ad = smem_u32(KVl + (kb + (lane & 7)) * 72 +
                              kk * 16 + ((lane >> 3) & 1) * 8);
                LDSM_X2(bfl[t], ad);
            }
#pragma unroll
            for (int t = 0; t < 4; t++) MMA_STEP(qfh[kk], bfh[t], acc[t]);
#pragma unroll
            for (int t = 0; t < 4; t++) MMA_STEP(qfl[kk], bfh[t], acc[t]);
#pragma unroll
            for (int t = 0; t < 4; t++) MMA_STEP(qfh[kk], bfl[t], acc[t]);
        }

        int row = wm * 16 + (lane >> 2);
#pragma unroll
        for (int t = 0; t < 4; t++) {
            int col = kc + wn * 32 + t * 8 + 2 * (lane & 3);
            *(float2*)&S[row * 1028 + col] = make_float2(acc[t][0], acc[t][1]);
            *(float2*)&S[(row + 8) * 1028 + col] = make_float2(acc[t][2], acc[t][3]);
        }
    }
    __syncthreads();

    // ---- mask + softmax: 8 threads per row ----
    {
        const int row = tid >> 3, c0 = tid & 7;
        const unsigned char* m8 = (const unsigned char*)mask;
        const int* m32 = (const int*)mask;
        size_t mbase = ((size_t)b_ * L + q0 + row) * L;
        float* Sr = S + row * 1028;

        float mx = -3.4e38f;
        for (int k = 0; k < 128; k++) {
            int c = c0 + 8 * k;
            bool mk = u8 ? (m8[mbase + c] != 0) : (m32[mbase + c] != 0);
            float s = mk ? -1e9f : Sr[c];
            Sr[c] = s;
            mx = fmaxf(mx, s);
        }
#pragma unroll
        for (int off = 4; off; off >>= 1)
            mx = fmaxf(mx, __shfl_xor_sync(0xffffffffu, mx, off));
        float sum = 0.f;
        for (int k = 0; k < 128; k++) {
            int c = c0 + 8 * k;
            float e_ = __expf(Sr[c] - mx);
            Sr[c] = e_;
            sum += e_;
        }
#pragma unroll
        for (int off = 4; off; off >>= 1)
            sum += __shfl_xor_sync(0xffffffffu, sum, off);
        float inv = 1.f / sum;
        for (int k = 0; k < 128; k++) Sr[c0 + 8 * k] *= inv;
    }
    __syncthreads();

    // ---- attn probabilities out (coalesced float4) ----
    if (attn_out) {
        for (int idx = tid; idx < 32 * 256; idx += 256) {
            int r = idx >> 8, c4 = (idx & 255) * 4;
            float4 v = *(float4*)&S[r * 1028 + c4];
            *(float4*)&attn_out[((size_t)bh * L + q0 + r) * L + c4] = v;
        }
    }

    // ---- context: C[32][64] = P @ V, 8 chunks ----
    float cacc[2][4];
#pragma unroll
    for (int t = 0; t < 2; t++)
#pragma unroll
        for (int f = 0; f < 4; f++) cacc[t][f] = 0.f;

    for (int kc = 0; kc < L; kc += 128) {
        __syncthreads();
        {
            int r = tid >> 1, d0 = (tid & 1) * 32;
            const uint4* sh = (const uint4*)(g_Vh + ((size_t)bh * L + kc + r) * DK + d0);
            const uint4* sl = (const uint4*)(g_Vl + ((size_t)bh * L + kc + r) * DK + d0);
            uint4* dh = (uint4*)(KVh + r * 72 + d0);
            uint4* dl = (uint4*)(KVl + r * 72 + d0);
#pragma unroll
            for (int i = 0; i < 4; i++) { dh[i] = sh[i]; dl[i] = sl[i]; }
        }
        // convert P chunk [32][128] to bf16 hi/lo
        {
            int r = tid >> 3, cb = (tid & 7) * 16;
            const float* Sr = S + r * 1028 + kc + cb;
#pragma unroll
            for (int i = 0; i < 16; i += 2) {
                float p0 = Sr[i], p1 = Sr[i + 1];
                __nv_bfloat16 h0 = __float2bfloat16(p0);
                __nv_bfloat16 h1 = __float2bfloat16(p1);
                *(__nv_bfloat162*)(Ph + r * 136 + cb + i) = __nv_bfloat162(h0, h1);
                *(__nv_bfloat162*)(Pl + r * 136 + cb + i) = __nv_bfloat162(
                    __float2bfloat16(p0 - __bfloat162float(h0)),
                    __float2bfloat16(p1 - __bfloat162float(h1)));
            }
        }
        __syncthreads();

#pragma unroll
        for (int kk = 0; kk < 8; kk++) {
            uint32_t pah[4], pal[4], bvh[2][2], bvl[2][2];
            uint32_t ad = smem_u32(Ph + (wm * 16 + (lane & 15)) * 136 +
                                   kk * 16 + (lane >> 4) * 8);
            LDSM_X4(pah, ad);
            ad = smem_u32(Pl + (wm * 16 + (lane & 15)) * 136 +
                          kk * 16 + (lane >> 4) * 8);
            LDSM_X4(pal, ad);
#pragma unroll
            for (int t = 0; t < 2; t++) {
                ad = smem_u32(KVh + (kk * 16 + (lane & 15)) * 72 +
                              wn * 16 + t * 8);
                LDSM_X2T(bvh[t], ad);
                ad = smem_u32(KVl + (kk * 16 + (lane & 15)) * 72 +
                              wn * 16 + t * 8);
                LDSM_X2T(bvl[t], ad);
            }
#pragma unroll
            for (int t = 0; t < 2; t++) MMA_STEP(pah, bvh[t], cacc[t]);
#pragma unroll
            for (int t = 0; t < 2; t++) MMA_STEP(pal, bvh[t], cacc[t]);
#pragma unroll
            for (int t = 0; t < 2; t++) MMA_STEP(pah, bvl[t], cacc[t]);
        }
    }

    // ---- write context as bf16 split 2D [B*L][1024] ----
    {
        int h_ = bh & 15;
        int row = q0 + wm * 16 + (lane >> 2);
#pragma unroll
        for (int t = 0; t < 2; t++) {
            int d = wn * 16 + t * 8 + 2 * (lane & 3);
#pragma unroll
            for (int hrow = 0; hrow < 2; hrow++) {
                float v0 = cacc[t][hrow * 2 + 0];
                float v1 = cacc[t][hrow * 2 + 1];
                __nv_bfloat16 h0 = __float2bfloat16(v0);
                __nv_bfloat16 h1 = __float2bfloat16(v1);
                size_t off = ((size_t)(b_ * L) + row + hrow * 8) * DM + h_ * 64 + d;
                *(__nv_bfloat162*)(g_Ch + off) = __nv_bfloat162(h0, h1);
                *(__nv_bfloat162*)(g_Cl + off) = __nv_bfloat162(
                    __float2bfloat16(v0 - __bfloat162float(h0)),
                    __float2bfloat16(v1 - __bfloat162float(h1)));
            }
        }
    }
}

// ---------------- layernorm --------------------------------------------------
__global__ __launch_bounds__(256) void ln_kernel(
    const float* __restrict__ gamma, const float* __restrict__ beta,
    float* __restrict__ out)
{
    __shared__ float red[18];
    const int r = blockIdx.x, tid = threadIdx.x;
    const float4* x4 = (const float4*)(g_preln + (size_t)r * DM);
    float4 v = x4[tid];

    float s = v.x + v.y + v.z + v.w;
#pragma unroll
    for (int off = 16; off; off >>= 1) s += __shfl_xor_sync(0xffffffffu, s, off);
    if ((tid & 31) == 0) red[tid >> 5] = s;
    __syncthreads();
    if (tid == 0) {
        float t = 0.f;
        for (int i = 0; i < 8; i++) t += red[i];
        red[16] = t * (1.f / 1024.f);
    }
    __syncthreads();
    float mean = red[16];

    float dx = v.x - mean, dy = v.y - mean, dz = v.z - mean, dw = v.w - mean;
    float ss = dx * dx + dy * dy + dz * dz + dw * dw;
#pragma unroll
    for (int off = 16; off; off >>= 1) ss += __shfl_xor_sync(0xffffffffu, ss, off);
    if ((tid & 31) == 0) red[8 + (tid >> 5)] = ss;
    __syncthreads();
    if (tid == 0) {
        float t = 0.f;
        for (int i = 0; i < 8; i++) t += red[8 + i];
        red[17] = rsqrtf(t * (1.f / 1024.f) + 1e-6f);
    }
    __syncthreads();
    float rs = red[17];

    float4 g = ((const float4*)gamma)[tid];
    float4 bb = ((const float4*)beta)[tid];
    float4 o;
    o.x = dx * rs * g.x + bb.x;
    o.y = dy * rs * g.y + bb.y;
    o.z = dz * rs * g.z + bb.z;
    o.w = dw * rs * g.w + bb.w;

    float* op = out ? (out + (size_t)r * DM) : (g_preln + (size_t)r * DM);
    ((float4*)op)[tid] = o;
}

// ---------------- launch -----------------------------------------------------
extern "C" void kernel_launch(void* const* d_in, const int* in_sizes, int n_in,
                              void* d_out, int out_size)
{
    const float* X     = (const float*)d_in[0];
    const void*  mask  = d_in[1];
    const float* Wq    = (const float*)d_in[2];
    const float* Wk    = (const float*)d_in[3];
    const float* Wv    = (const float*)d_in[4];
    const float* Wo    = (const float*)d_in[5];
    const float* gamma = (const float*)d_in[6];
    const float* beta  = (const float*)d_in[7];

    const long long LNN = (long long)B * L * DM;
    const long long ATT = (long long)BH * L * L;

    float* out_ln = nullptr;
    float* out_attn = nullptr;
    long long os = (long long)out_size;
    if (os >= LNN + ATT) {
        out_ln = (float*)d_out;
        out_attn = (float*)d_out + LNN;
    } else if (os == ATT) {
        out_attn = (float*)d_out;
    } else {
        out_ln = (float*)d_out;
    }

    detect_mask_kernel<<<1, 256>>>((const unsigned int*)mask);

    __nv_bfloat16 *Xh, *Xl, *Wh0, *Wl0;
    cudaGetSymbolAddress((void**)&Xh, g_Xh);
    cudaGetSymbolAddress((void**)&Xl, g_Xl);
    cudaGetSymbolAddress((void**)&Wh0, g_Wh);
    cudaGetSymbolAddress((void**)&Wl0, g_Wl);

    int nX4 = (B * L * DM) / 4;
    int nW4 = (DM * DM) / 4;
    cvt_split_kernel<<<(nX4 + 255) / 256, 256>>>((const float4*)X, Xh, Xl, nX4);
    cvt_split_kernel<<<(nW4 + 255) / 256, 256>>>((const float4*)Wq,
        Wh0 + 0 * (size_t)DM * DM, Wl0 + 0 * (size_t)DM * DM, nW4);
    cvt_split_kernel<<<(nW4 + 255) / 256, 256>>>((const float4*)Wk,
        Wh0 + 1 * (size_t)DM * DM, Wl0 + 1 * (size_t)DM * DM, nW4);
    cvt_split_kernel<<<(nW4 + 255) / 256, 256>>>((const float4*)Wv,
        Wh0 + 2 * (size_t)DM * DM, Wl0 + 2 * (size_t)DM * DM, nW4);
    cvt_split_kernel<<<(nW4 + 255) / 256, 256>>>((const float4*)Wo,
        Wh0 + 3 * (size_t)DM * DM, Wl0 + 3 * (size_t)DM * DM, nW4);

    qkv_mma_kernel<<<dim3(8, 64, 3), 256>>>();

    cudaFuncSetAttribute(attn_mma_kernel,
                         cudaFuncAttributeMaxDynamicSharedMemorySize, ATTN_SMEM);
    attn_mma_kernel<<<dim3(L / 32, BH), 256, ATTN_SMEM>>>(mask, out_attn);

    oproj_mma_kernel<<<dim3(8, 64), 256>>>(X);
    ln_kernel<<<B * L, 256>>>(gamma, beta, out_ln);
}

// round 9
// speedup vs baseline: 2.6525x; 1.0854x over previous
#include <cuda_runtime.h>
#include <cuda_bf16.h>
#include <cstdint>
#include <cstddef>

#define B 8
#define L 1024
#define H 16
#define DK 64
#define DM 1024
#define BH (B*H)

// ---------------- scratch ----------------------------------------------------
__device__ float g_preln[(size_t)B * L * DM];
__device__ int   g_mask_u8;

__device__ __nv_bfloat16 g_Xh[(size_t)B * L * DM];
__device__ __nv_bfloat16 g_Xl[(size_t)B * L * DM];
__device__ __nv_bfloat16 g_Wh[4][(size_t)DM * DM];   // q,k,v,o
__device__ __nv_bfloat16 g_Wl[4][(size_t)DM * DM];
__device__ __nv_bfloat16 g_Qh[(size_t)BH * L * DK];  // pre-scaled by 0.125
__device__ __nv_bfloat16 g_Ql[(size_t)BH * L * DK];
__device__ __nv_bfloat16 g_Kh[(size_t)BH * L * DK];
__device__ __nv_bfloat16 g_Kl[(size_t)BH * L * DK];
__device__ __nv_bfloat16 g_Vh[(size_t)BH * L * DK];
__device__ __nv_bfloat16 g_Vl[(size_t)BH * L * DK];
__device__ __nv_bfloat16 g_Ch[(size_t)B * L * DM];
__device__ __nv_bfloat16 g_Cl[(size_t)B * L * DM];

__device__ __forceinline__ uint32_t smem_u32(const void* p) {
    return (uint32_t)__cvta_generic_to_shared(p);
}

#define MMA_STEP(afr, bfr, accp)                                              \
    asm volatile(                                                              \
        "mma.sync.aligned.m16n8k16.row.col.f32.bf16.bf16.f32 "                 \
        "{%0,%1,%2,%3},{%4,%5,%6,%7},{%8,%9},{%0,%1,%2,%3};"                   \
        : "+f"((accp)[0]), "+f"((accp)[1]), "+f"((accp)[2]), "+f"((accp)[3])   \
        : "r"((afr)[0]), "r"((afr)[1]), "r"((afr)[2]), "r"((afr)[3]),          \
          "r"((bfr)[0]), "r"((bfr)[1]))

#define LDSM_X4(frag, ad)                                                      \
    asm volatile("ldmatrix.sync.aligned.m8n8.x4.shared.b16 {%0,%1,%2,%3},[%4];"\
        : "=r"((frag)[0]), "=r"((frag)[1]), "=r"((frag)[2]), "=r"((frag)[3])   \
        : "r"(ad))

#define LDSM_X2(frag, ad)                                                      \
    asm volatile("ldmatrix.sync.aligned.m8n8.x2.shared.b16 {%0,%1},[%2];"      \
        : "=r"((frag)[0]), "=r"((frag)[1]) : "r"(ad))

#define LDSM_X2T(frag, ad)                                                     \
    asm volatile("ldmatrix.sync.aligned.m8n8.x2.trans.shared.b16 {%0,%1},[%2];"\
        : "=r"((frag)[0]), "=r"((frag)[1]) : "r"(ad))

// ---------------- mask dtype detection --------------------------------------
__global__ void detect_mask_kernel(const unsigned int* __restrict__ m)
{
    __shared__ int s_any;
    if (threadIdx.x == 0) s_any = 0;
    __syncthreads();
    int any = 0;
    for (int i = threadIdx.x; i < 16384; i += 256)
        if (m[i] > 1u) any = 1;
    if (any) atomicOr(&s_any, 1);
    __syncthreads();
    if (threadIdx.x == 0) g_mask_u8 = s_any;
}

// ---------------- fp32 -> bf16 hi/lo split ----------------------------------
__global__ __launch_bounds__(256) void cvt_split_kernel(
    const float4* __restrict__ in, __nv_bfloat16* __restrict__ h,
    __nv_bfloat16* __restrict__ l, int n4)
{
    int i = blockIdx.x * 256 + threadIdx.x;
    if (i >= n4) return;
    float4 v = in[i];
    __nv_bfloat16 h0 = __float2bfloat16(v.x);
    __nv_bfloat16 h1 = __float2bfloat16(v.y);
    __nv_bfloat16 h2 = __float2bfloat16(v.z);
    __nv_bfloat16 h3 = __float2bfloat16(v.w);
    __nv_bfloat162* hp = (__nv_bfloat162*)(h + (size_t)i * 4);
    hp[0] = __nv_bfloat162(h0, h1);
    hp[1] = __nv_bfloat162(h2, h3);
    __nv_bfloat162* lp = (__nv_bfloat162*)(l + (size_t)i * 4);
    lp[0] = __nv_bfloat162(__float2bfloat16(v.x - __bfloat162float(h0)),
                           __float2bfloat16(v.y - __bfloat162float(h1)));
    lp[1] = __nv_bfloat162(__float2bfloat16(v.z - __bfloat162float(h2)),
                           __float2bfloat16(v.w - __bfloat162float(h3)));
}

// ---------------- mma.sync bf16 split GEMM core ------------------------------
#define GEMM_MAIN(AH, AL, BH_, BL_)                                            \
    __shared__ __nv_bfloat16 sA[2][128][40];                                   \
    __shared__ __nv_bfloat16 sB[2][32][136];                                   \
    const int tid = threadIdx.x, lane = tid & 31, warp = tid >> 5;             \
    const int wm = warp >> 2, wn = warp & 3;                                   \
    const int row0 = blockIdx.y * 128, col0 = blockIdx.x * 128;                \
    float acc[4][4][4];                                                        \
    _Pragma("unroll") for (int i = 0; i < 4; i++)                              \
    _Pragma("unroll") for (int j = 0; j < 4; j++)                              \
    _Pragma("unroll") for (int f = 0; f < 4; f++) acc[i][j][f] = 0.f;          \
    const int ar = tid >> 1, ac = (tid & 1) * 16;                              \
    const int br = tid >> 3, bc = (tid & 7) * 8;                               \
    {                                                                          \
        uint4 a0 = *(const uint4*)(AH + (size_t)(row0 + ar) * DM + ac);        \
        uint4 a1 = *(const uint4*)(AH + (size_t)(row0 + ar) * DM + ac + 8);    \
        uint4 b0 = *(const uint4*)(BH_ + (size_t)br * DM + col0 + bc);         \
        uint4 b1 = *(const uint4*)(BH_ + (size_t)br * DM + col0 + bc + 64);    \
        *(uint4*)&sA[0][ar][ac] = a0;  *(uint4*)&sA[0][ar][ac + 8] = a1;       \
        *(uint4*)&sB[0][br][bc] = b0;  *(uint4*)&sB[0][br][bc + 64] = b1;      \
    }                                                                          \
    __syncthreads();                                                           \
    int buf = 0;                                                               \
    for (int cc = 0; cc < 96; cc++) {                                          \
        uint4 a0, a1, b0, b1;                                                  \
        const bool nxt = (cc + 1) < 96;                                        \
        if (nxt) {                                                             \
            int ph = (cc + 1) >> 5, k0 = ((cc + 1) & 31) * 32;                 \
            const __nv_bfloat16* Ap = (ph == 1) ? AL : AH;                     \
            const __nv_bfloat16* Bp = (ph == 2) ? BL_ : BH_;                   \
            a0 = *(const uint4*)(Ap + (size_t)(row0 + ar) * DM + k0 + ac);     \
            a1 = *(const uint4*)(Ap + (size_t)(row0 + ar) * DM + k0 + ac + 8); \
            b0 = *(const uint4*)(Bp + (size_t)(k0 + br) * DM + col0 + bc);     \
            b1 = *(const uint4*)(Bp + (size_t)(k0 + br) * DM + col0 + bc + 64);\
        }                                                                      \
        _Pragma("unroll")                                                      \
        for (int ks = 0; ks < 32; ks += 16) {                                  \
            uint32_t afr[4][4], bfr[4][2];                                     \
            _Pragma("unroll")                                                  \
            for (int i = 0; i < 4; i++) {                                      \
                uint32_t ad = smem_u32(                                        \
                    &sA[buf][wm * 64 + i * 16 + (lane & 15)]                   \
                        [ks + (lane >> 4) * 8]);                               \
                LDSM_X4(afr[i], ad);                                           \
            }                                                                  \
            _Pragma("unroll")                                                  \
            for (int j = 0; j < 4; j++) {                                      \
                uint32_t bd = smem_u32(                                        \
                    &sB[buf][ks + (lane & 15)][wn * 32 + j * 8]);              \
                LDSM_X2T(bfr[j], bd);                                          \
            }                                                                  \
            _Pragma("unroll")                                                  \
            for (int i = 0; i < 4; i++)                                        \
            _Pragma("unroll")                                                  \
            for (int j = 0; j < 4; j++) MMA_STEP(afr[i], bfr[j], acc[i][j]);   \
        }                                                                      \
        if (nxt) {                                                             \
            *(uint4*)&sA[buf ^ 1][ar][ac] = a0;                                \
            *(uint4*)&sA[buf ^ 1][ar][ac + 8] = a1;                            \
            *(uint4*)&sB[buf ^ 1][br][bc] = b0;                                \
            *(uint4*)&sB[buf ^ 1][br][bc + 64] = b1;                           \
        }                                                                      \
        __syncthreads();                                                       \
        buf ^= 1;                                                              \
    }

// QKV: writes bf16 hi/lo splits directly (Q pre-scaled by 0.125)
__global__ __launch_bounds__(256) void qkv_mma_kernel()
{
    const int z = blockIdx.z;
    const __nv_bfloat16* BHp = g_Wh[z];
    const __nv_bfloat16* BLp = g_Wl[z];

    GEMM_MAIN(g_Xh, g_Xl, BHp, BLp)

    __nv_bfloat16* Oh = (z == 0) ? g_Qh : (z == 1) ? g_Kh : g_Vh;
    __nv_bfloat16* Ol = (z == 0) ? g_Ql : (z == 1) ? g_Kl : g_Vl;
    const float sc = (z == 0) ? 0.125f : 1.0f;

    const int lr = lane >> 2, lc = (lane & 3) * 2;
#pragma unroll
    for (int i = 0; i < 4; i++) {
        int r0 = row0 + wm * 64 + i * 16 + lr;
#pragma unroll
        for (int j = 0; j < 4; j++) {
            int c = col0 + wn * 32 + j * 8 + lc;
            int h_ = c >> 6, d_ = c & 63;
#pragma unroll
            for (int hrow = 0; hrow < 2; hrow++) {
                int r = r0 + hrow * 8;
                int b_ = r >> 10, l_ = r & 1023;
                float v0 = acc[i][j][hrow * 2 + 0] * sc;
                float v1 = acc[i][j][hrow * 2 + 1] * sc;
                __nv_bfloat16 h0 = __float2bfloat16(v0);
                __nv_bfloat16 h1 = __float2bfloat16(v1);
                size_t off = (((size_t)(b_ * H + h_)) * L + l_) * DK + d_;
                *(__nv_bfloat162*)(Oh + off) = __nv_bfloat162(h0, h1);
                *(__nv_bfloat162*)(Ol + off) = __nv_bfloat162(
                    __float2bfloat16(v0 - __bfloat162float(h0)),
                    __float2bfloat16(v1 - __bfloat162float(h1)));
            }
        }
    }
}

__global__ __launch_bounds__(256) void oproj_mma_kernel(const float* __restrict__ X)
{
    GEMM_MAIN(g_Ch, g_Cl, g_Wh[3], g_Wl[3])

    const int lr = lane >> 2, lc = (lane & 3) * 2;
#pragma unroll
    for (int i = 0; i < 4; i++) {
        int r0 = row0 + wm * 64 + i * 16 + lr;
#pragma unroll
        for (int j = 0; j < 4; j++) {
            int c = col0 + wn * 32 + j * 8 + lc;
#pragma unroll
            for (int hrow = 0; hrow < 2; hrow++) {
                int r = r0 + hrow * 8;
                float2 xv = *(const float2*)&X[(size_t)r * DM + c];
                float2 o;
                o.x = acc[i][j][hrow * 2 + 0] + xv.x;
                o.y = acc[i][j][hrow * 2 + 1] + xv.y;
                *(float2*)&g_preln[(size_t)r * DM + c] = o;
            }
        }
    }
}

// ---------------- tensor-core attention --------------------------------------
#define SOFF_Q  131584
#define SOFF_K  140800
#define SOFF_P  177664
#define ATTN_SMEM 195072

__global__ __launch_bounds__(256) void attn_mma_kernel(
    const void* __restrict__ mask, float* __restrict__ attn_out)
{
    extern __shared__ char smx[];
    float* S = (float*)smx;
    __nv_bfloat16* Qsh = (__nv_bfloat16*)(smx + SOFF_Q);
    __nv_bfloat16* Qsl = Qsh + 32 * 72;
    __nv_bfloat16* KVh = (__nv_bfloat16*)(smx + SOFF_K);
    __nv_bfloat16* KVl = KVh + 128 * 72;
    __nv_bfloat16* Ph  = (__nv_bfloat16*)(smx + SOFF_P);
    __nv_bfloat16* Pl  = Ph + 32 * 136;

    const int tid = threadIdx.x, lane = tid & 31, warp = tid >> 5;
    const int wm = warp >> 2, wn = warp & 3;
    const int bh = blockIdx.y, b_ = bh >> 4, q0 = blockIdx.x * 32;
    const int u8 = g_mask_u8;

    {
        int r = tid >> 3, d0 = (tid & 7) * 8;
        *(uint4*)(Qsh + r * 72 + d0) =
            *(const uint4*)(g_Qh + ((size_t)bh * L + q0 + r) * DK + d0);
        *(uint4*)(Qsl + r * 72 + d0) =
            *(const uint4*)(g_Ql + ((size_t)bh * L + q0 + r) * DK + d0);
    }
    __syncthreads();

    uint32_t qfh[4][4], qfl[4][4];
#pragma unroll
    for (int kk = 0; kk < 4; kk++) {
        uint32_t ad = smem_u32(Qsh + (wm * 16 + (lane & 15)) * 72 +
                               kk * 16 + (lane >> 4) * 8);
        LDSM_X4(qfh[kk], ad);
        ad = smem_u32(Qsl + (wm * 16 + (lane & 15)) * 72 +
                      kk * 16 + (lane >> 4) * 8);
        LDSM_X4(qfl[kk], ad);
    }

    for (int kc = 0; kc < L; kc += 128) {
        __syncthreads();
        {
            int r = tid >> 1, d0 = (tid & 1) * 32;
            const uint4* sh = (const uint4*)(g_Kh + ((size_t)bh * L + kc + r) * DK + d0);
            const uint4* sl = (const uint4*)(g_Kl + ((size_t)bh * L + kc + r) * DK + d0);
            uint4* dh = (uint4*)(KVh + r * 72 + d0);
            uint4* dl = (uint4*)(KVl + r * 72 + d0);
#pragma unroll
            for (int i = 0; i < 4; i++) { dh[i] = sh[i]; dl[i] = sl[i]; }
        }
        __syncthreads();

        float acc[4][4];
#pragma unroll
        for (int t = 0; t < 4; t++)
#pragma unroll
            for (int f = 0; f < 4; f++) acc[t][f] = 0.f;

#pragma unroll
        for (int kk = 0; kk < 4; kk++) {
            uint32_t bfh[4][2], bfl[4][2];
#pragma unroll
            for (int t = 0; t < 4; t++) {
                int kb = wn * 32 + t * 8;
                uint32_t ad = smem_u32(KVh + (kb + (lane & 7)) * 72 +
                                       kk * 16 + ((lane >> 3) & 1) * 8);
                LDSM_X2(bfh[t], ad);
                ad = smem_u32(KVl + (kb + (lane & 7)) * 72 +
                              kk * 16 + ((lane >> 3) & 1) * 8);
                LDSM_X2(bfl[t], ad);
            }
#pragma unroll
            for (int t = 0; t < 4; t++) MMA_STEP(qfh[kk], bfh[t], acc[t]);
#pragma unroll
            for (int t = 0; t < 4; t++) MMA_STEP(qfl[kk], bfh[t], acc[t]);
#pragma unroll
            for (int t = 0; t < 4; t++) MMA_STEP(qfh[kk], bfl[t], acc[t]);
        }

        int row = wm * 16 + (lane >> 2);
#pragma unroll
        for (int t = 0; t < 4; t++) {
            int col = kc + wn * 32 + t * 8 + 2 * (lane & 3);
            *(float2*)&S[row * 1028 + col] = make_float2(acc[t][0], acc[t][1]);
            *(float2*)&S[(row + 8) * 1028 + col] = make_float2(acc[t][2], acc[t][3]);
        }
    }
    __syncthreads();

    // ---- mask + softmax + normalize + attn_out: all float4 vectorized ------
    {
        const int row = tid >> 3, c0 = tid & 7;
        float* Sr = S + row * 1028;
        size_t mbase = ((size_t)b_ * L + q0 + row) * L;

        // pass 1: apply mask, find max
        float mx = -3.4e38f;
        if (u8) {
            const unsigned char* m8 = (const unsigned char*)mask + mbase;
#pragma unroll 4
            for (int k = 0; k < 32; k++) {
                int c = (c0 + 8 * k) * 4;
                float4 v = *(float4*)&Sr[c];
                uint32_t mw = *(const uint32_t*)(m8 + c);
                if (mw & 0x000000ffu) v.x = -1e9f;
                if (mw & 0x0000ff00u) v.y = -1e9f;
                if (mw & 0x00ff0000u) v.z = -1e9f;
                if (mw & 0xff000000u) v.w = -1e9f;
                *(float4*)&Sr[c] = v;
                mx = fmaxf(mx, fmaxf(fmaxf(v.x, v.y), fmaxf(v.z, v.w)));
            }
        } else {
            const int* m32 = (const int*)mask + mbase;
#pragma unroll 4
            for (int k = 0; k < 32; k++) {
                int c = (c0 + 8 * k) * 4;
                float4 v = *(float4*)&Sr[c];
                int4 mw = *(const int4*)(m32 + c);
                if (mw.x) v.x = -1e9f;
                if (mw.y) v.y = -1e9f;
                if (mw.z) v.z = -1e9f;
                if (mw.w) v.w = -1e9f;
                *(float4*)&Sr[c] = v;
                mx = fmaxf(mx, fmaxf(fmaxf(v.x, v.y), fmaxf(v.z, v.w)));
            }
        }
#pragma unroll
        for (int off = 4; off; off >>= 1)
            mx = fmaxf(mx, __shfl_xor_sync(0xffffffffu, mx, off));

        // pass 2: exp + sum
        float sum = 0.f;
#pragma unroll 4
        for (int k = 0; k < 32; k++) {
            int c = (c0 + 8 * k) * 4;
            float4 v = *(float4*)&Sr[c];
            v.x = __expf(v.x - mx);
            v.y = __expf(v.y - mx);
            v.z = __expf(v.z - mx);
            v.w = __expf(v.w - mx);
            *(float4*)&Sr[c] = v;
            sum += v.x + v.y + v.z + v.w;
        }
#pragma unroll
        for (int off = 4; off; off >>= 1)
            sum += __shfl_xor_sync(0xffffffffu, sum, off);
        float inv = 1.f / sum;

        // pass 3: normalize; write back to S and to attn_out
        float* Ar = attn_out ? (attn_out + ((size_t)bh * L + q0 + row) * L) : nullptr;
#pragma unroll 4
        for (int k = 0; k < 32; k++) {
            int c = (c0 + 8 * k) * 4;
            float4 v = *(float4*)&Sr[c];
            v.x *= inv; v.y *= inv; v.z *= inv; v.w *= inv;
            *(float4*)&Sr[c] = v;
            if (Ar) *(float4*)&Ar[c] = v;
        }
    }
    __syncthreads();

    // ---- context: C[32][64] = P @ V, 8 chunks ----
    float cacc[2][4];
#pragma unroll
    for (int t = 0; t < 2; t++)
#pragma unroll
        for (int f = 0; f < 4; f++) cacc[t][f] = 0.f;

    for (int kc = 0; kc < L; kc += 128) {
        __syncthreads();
        {
            int r = tid >> 1, d0 = (tid & 1) * 32;
            const uint4* sh = (const uint4*)(g_Vh + ((size_t)bh * L + kc + r) * DK + d0);
            const uint4* sl = (const uint4*)(g_Vl + ((size_t)bh * L + kc + r) * DK + d0);
            uint4* dh = (uint4*)(KVh + r * 72 + d0);
            uint4* dl = (uint4*)(KVl + r * 72 + d0);
#pragma unroll
            for (int i = 0; i < 4; i++) { dh[i] = sh[i]; dl[i] = sl[i]; }
        }
        // convert P chunk [32][128] to bf16 hi/lo (float4 loads)
        {
            int r = tid >> 3, cb = (tid & 7) * 16;
            const float* Sr = S + r * 1028 + kc + cb;
#pragma unroll
            for (int i = 0; i < 16; i += 4) {
                float4 p = *(const float4*)&Sr[i];
                __nv_bfloat16 h0 = __float2bfloat16(p.x);
                __nv_bfloat16 h1 = __float2bfloat16(p.y);
                __nv_bfloat16 h2 = __float2bfloat16(p.z);
                __nv_bfloat16 h3 = __float2bfloat16(p.w);
                __nv_bfloat162* php = (__nv_bfloat162*)(Ph + r * 136 + cb + i);
                php[0] = __nv_bfloat162(h0, h1);
                php[1] = __nv_bfloat162(h2, h3);
                __nv_bfloat162* plp = (__nv_bfloat162*)(Pl + r * 136 + cb + i);
                plp[0] = __nv_bfloat162(
                    __float2bfloat16(p.x - __bfloat162float(h0)),
                    __float2bfloat16(p.y - __bfloat162float(h1)));
                plp[1] = __nv_bfloat162(
                    __float2bfloat16(p.z - __bfloat162float(h2)),
                    __float2bfloat16(p.w - __bfloat162float(h3)));
            }
        }
        __syncthreads();

#pragma unroll
        for (int kk = 0; kk < 8; kk++) {
            uint32_t pah[4], pal[4], bvh[2][2], bvl[2][2];
            uint32_t ad = smem_u32(Ph + (wm * 16 + (lane & 15)) * 136 +
                                   kk * 16 + (lane >> 4) * 8);
            LDSM_X4(pah, ad);
            ad = smem_u32(Pl + (wm * 16 + (lane & 15)) * 136 +
                          kk * 16 + (lane >> 4) * 8);
            LDSM_X4(pal, ad);
#pragma unroll
            for (int t = 0; t < 2; t++) {
                ad = smem_u32(KVh + (kk * 16 + (lane & 15)) * 72 +
                              wn * 16 + t * 8);
                LDSM_X2T(bvh[t], ad);
                ad = smem_u32(KVl + (kk * 16 + (lane & 15)) * 72 +
                              wn * 16 + t * 8);
                LDSM_X2T(bvl[t], ad);
            }
#pragma unroll
            for (int t = 0; t < 2; t++) MMA_STEP(pah, bvh[t], cacc[t]);
#pragma unroll
            for (int t = 0; t < 2; t++) MMA_STEP(pal, bvh[t], cacc[t]);
#pragma unroll
            for (int t = 0; t < 2; t++) MMA_STEP(pah, bvl[t], cacc[t]);
        }
    }

    {
        int h_ = bh & 15;
        int row = q0 + wm * 16 + (lane >> 2);
#pragma unroll
        for (int t = 0; t < 2; t++) {
            int d = wn * 16 + t * 8 + 2 * (lane & 3);
#pragma unroll
            for (int hrow = 0; hrow < 2; hrow++) {
                float v0 = cacc[t][hrow * 2 + 0];
                float v1 = cacc[t][hrow * 2 + 1];
                __nv_bfloat16 h0 = __float2bfloat16(v0);
                __nv_bfloat16 h1 = __float2bfloat16(v1);
                size_t off = ((size_t)(b_ * L) + row + hrow * 8) * DM + h_ * 64 + d;
                *(__nv_bfloat162*)(g_Ch + off) = __nv_bfloat162(h0, h1);
                *(__nv_bfloat162*)(g_Cl + off) = __nv_bfloat162(
                    __float2bfloat16(v0 - __bfloat162float(h0)),
                    __float2bfloat16(v1 - __bfloat162float(h1)));
            }
        }
    }
}

// ---------------- layernorm --------------------------------------------------
__global__ __launch_bounds__(256) void ln_kernel(
    const float* __restrict__ gamma, const float* __restrict__ beta,
    float* __restrict__ out)
{
    __shared__ float red[18];
    const int r = blockIdx.x, tid = threadIdx.x;
    const float4* x4 = (const float4*)(g_preln + (size_t)r * DM);
    float4 v = x4[tid];

    float s = v.x + v.y + v.z + v.w;
#pragma unroll
    for (int off = 16; off; off >>= 1) s += __shfl_xor_sync(0xffffffffu, s, off);
    if ((tid & 31) == 0) red[tid >> 5] = s;
    __syncthreads();
    if (tid == 0) {
        float t = 0.f;
        for (int i = 0; i < 8; i++) t += red[i];
        red[16] = t * (1.f / 1024.f);
    }
    __syncthreads();
    float mean = red[16];

    float dx = v.x - mean, dy = v.y - mean, dz = v.z - mean, dw = v.w - mean;
    float ss = dx * dx + dy * dy + dz * dz + dw * dw;
#pragma unroll
    for (int off = 16; off; off >>= 1) ss += __shfl_xor_sync(0xffffffffu, ss, off);
    if ((tid & 31) == 0) red[8 + (tid >> 5)] = ss;
    __syncthreads();
    if (tid == 0) {
        float t = 0.f;
        for (int i = 0; i < 8; i++) t += red[8 + i];
        red[17] = rsqrtf(t * (1.f / 1024.f) + 1e-6f);
    }
    __syncthreads();
    float rs = red[17];

    float4 g = ((const float4*)gamma)[tid];
    float4 bb = ((const float4*)beta)[tid];
    float4 o;
    o.x = dx * rs * g.x + bb.x;
    o.y = dy * rs * g.y + bb.y;
    o.z = dz * rs * g.z + bb.z;
    o.w = dw * rs * g.w + bb.w;

    float* op = out ? (out + (size_t)r * DM) : (g_preln + (size_t)r * DM);
    ((float4*)op)[tid] = o;
}

// ---------------- launch -----------------------------------------------------
extern "C" void kernel_launch(void* const* d_in, const int* in_sizes, int n_in,
                              void* d_out, int out_size)
{
    const float* X     = (const float*)d_in[0];
    const void*  mask  = d_in[1];
    const float* Wq    = (const float*)d_in[2];
    const float* Wk    = (const float*)d_in[3];
    const float* Wv    = (const float*)d_in[4];
    const float* Wo    = (const float*)d_in[5];
    const float* gamma = (const float*)d_in[6];
    const float* beta  = (const float*)d_in[7];

    const long long LNN = (long long)B * L * DM;
    const long long ATT = (long long)BH * L * L;

    float* out_ln = nullptr;
    float* out_attn = nullptr;
    long long os = (long long)out_size;
    if (os >= LNN + ATT) {
        out_ln = (float*)d_out;
        out_attn = (float*)d_out + LNN;
    } else if (os == ATT) {
        out_attn = (float*)d_out;
    } else {
        out_ln = (float*)d_out;
    }

    detect_mask_kernel<<<1, 256>>>((const unsigned int*)mask);

    __nv_bfloat16 *Xh, *Xl, *Wh0, *Wl0;
    cudaGetSymbolAddress((void**)&Xh, g_Xh);
    cudaGetSymbolAddress((void**)&Xl, g_Xl);
    cudaGetSymbolAddress((void**)&Wh0, g_Wh);
    cudaGetSymbolAddress((void**)&Wl0, g_Wl);

    int nX4 = (B * L * DM) / 4;
    int nW4 = (DM * DM) / 4;
    cvt_split_kernel<<<(nX4 + 255) / 256, 256>>>((const float4*)X, Xh, Xl, nX4);
    cvt_split_kernel<<<(nW4 + 255) / 256, 256>>>((const float4*)Wq,
        Wh0 + 0 * (size_t)DM * DM, Wl0 + 0 * (size_t)DM * DM, nW4);
    cvt_split_kernel<<<(nW4 + 255) / 256, 256>>>((const float4*)Wk,
        Wh0 + 1 * (size_t)DM * DM, Wl0 + 1 * (size_t)DM * DM, nW4);
    cvt_split_kernel<<<(nW4 + 255) / 256, 256>>>((const float4*)Wv,
        Wh0 + 2 * (size_t)DM * DM, Wl0 + 2 * (size_t)DM * DM, nW4);
    cvt_split_kernel<<<(nW4 + 255) / 256, 256>>>((const float4*)Wo,
        Wh0 + 3 * (size_t)DM * DM, Wl0 + 3 * (size_t)DM * DM, nW4);

    qkv_mma_kernel<<<dim3(8, 64, 3), 256>>>();

    cudaFuncSetAttribute(attn_mma_kernel,
                         cudaFuncAttributeMaxDynamicSharedMemorySize, ATTN_SMEM);
    attn_mma_kernel<<<dim3(L / 32, BH), 256, ATTN_SMEM>>>(mask, out_attn);

    oproj_mma_kernel<<<dim3(8, 64), 256>>>(X);
    ln_kernel<<<B * L, 256>>>(gamma, beta, out_ln);
}

// round 10
// speedup vs baseline: 2.9927x; 1.1282x over previous
#include <cuda_runtime.h>
#include <cuda_bf16.h>
#include <cstdint>
#include <cstddef>

#define B 8
#define L 1024
#define H 16
#define DK 64
#define DM 1024
#define BH (B*H)

// ---------------- scratch ----------------------------------------------------
__device__ float g_preln[(size_t)B * L * DM];
__device__ int   g_mask_u8;

__device__ __nv_bfloat16 g_Xh[(size_t)B * L * DM];
__device__ __nv_bfloat16 g_Xl[(size_t)B * L * DM];
__device__ __nv_bfloat16 g_Wh[4][(size_t)DM * DM];   // q,k,v,o
__device__ __nv_bfloat16 g_Wl[4][(size_t)DM * DM];
__device__ __nv_bfloat16 g_Qh[(size_t)BH * L * DK];  // pre-scaled by 0.125
__device__ __nv_bfloat16 g_Ql[(size_t)BH * L * DK];
__device__ __nv_bfloat16 g_Kh[(size_t)BH * L * DK];
__device__ __nv_bfloat16 g_Kl[(size_t)BH * L * DK];
__device__ __nv_bfloat16 g_Vh[(size_t)BH * L * DK];
__device__ __nv_bfloat16 g_Vl[(size_t)BH * L * DK];
__device__ __nv_bfloat16 g_Ch[(size_t)B * L * DM];
__device__ __nv_bfloat16 g_Cl[(size_t)B * L * DM];

__device__ __forceinline__ uint32_t smem_u32(const void* p) {
    return (uint32_t)__cvta_generic_to_shared(p);
}

#define MMA_STEP(afr, bfr, accp)                                              \
    asm volatile(                                                              \
        "mma.sync.aligned.m16n8k16.row.col.f32.bf16.bf16.f32 "                 \
        "{%0,%1,%2,%3},{%4,%5,%6,%7},{%8,%9},{%0,%1,%2,%3};"                   \
        : "+f"((accp)[0]), "+f"((accp)[1]), "+f"((accp)[2]), "+f"((accp)[3])   \
        : "r"((afr)[0]), "r"((afr)[1]), "r"((afr)[2]), "r"((afr)[3]),          \
          "r"((bfr)[0]), "r"((bfr)[1]))

#define LDSM_X4(frag, ad)                                                      \
    asm volatile("ldmatrix.sync.aligned.m8n8.x4.shared.b16 {%0,%1,%2,%3},[%4];"\
        : "=r"((frag)[0]), "=r"((frag)[1]), "=r"((frag)[2]), "=r"((frag)[3])   \
        : "r"(ad))

#define LDSM_X2(frag, ad)                                                      \
    asm volatile("ldmatrix.sync.aligned.m8n8.x2.shared.b16 {%0,%1},[%2];"      \
        : "=r"((frag)[0]), "=r"((frag)[1]) : "r"(ad))

#define LDSM_X2T(frag, ad)                                                     \
    asm volatile("ldmatrix.sync.aligned.m8n8.x2.trans.shared.b16 {%0,%1},[%2];"\
        : "=r"((frag)[0]), "=r"((frag)[1]) : "r"(ad))

__device__ __forceinline__ void cp16(uint32_t saddr, const void* g) {
    asm volatile("cp.async.ca.shared.global [%0], [%1], 16;" :: "r"(saddr), "l"(g));
}
#define CP_COMMIT()  asm volatile("cp.async.commit_group;" ::: "memory")
#define CP_WAIT0()   asm volatile("cp.async.wait_group 0;" ::: "memory")

// ---------------- mask dtype detection --------------------------------------
__global__ void detect_mask_kernel(const unsigned int* __restrict__ m)
{
    __shared__ int s_any;
    if (threadIdx.x == 0) s_any = 0;
    __syncthreads();
    int any = 0;
    for (int i = threadIdx.x; i < 16384; i += 256)
        if (m[i] > 1u) any = 1;
    if (any) atomicOr(&s_any, 1);
    __syncthreads();
    if (threadIdx.x == 0) g_mask_u8 = s_any;
}

// ---------------- fp32 -> bf16 hi/lo split ----------------------------------
__global__ __launch_bounds__(256) void cvt_split_kernel(
    const float4* __restrict__ in, __nv_bfloat16* __restrict__ h,
    __nv_bfloat16* __restrict__ l, int n4)
{
    int i = blockIdx.x * 256 + threadIdx.x;
    if (i >= n4) return;
    float4 v = in[i];
    __nv_bfloat16 h0 = __float2bfloat16(v.x);
    __nv_bfloat16 h1 = __float2bfloat16(v.y);
    __nv_bfloat16 h2 = __float2bfloat16(v.z);
    __nv_bfloat16 h3 = __float2bfloat16(v.w);
    __nv_bfloat162* hp = (__nv_bfloat162*)(h + (size_t)i * 4);
    hp[0] = __nv_bfloat162(h0, h1);
    hp[1] = __nv_bfloat162(h2, h3);
    __nv_bfloat162* lp = (__nv_bfloat162*)(l + (size_t)i * 4);
    lp[0] = __nv_bfloat162(__float2bfloat16(v.x - __bfloat162float(h0)),
                           __float2bfloat16(v.y - __bfloat162float(h1)));
    lp[1] = __nv_bfloat162(__float2bfloat16(v.z - __bfloat162float(h2)),
                           __float2bfloat16(v.w - __bfloat162float(h3)));
}

// ---------------- mma.sync bf16 split GEMM core ------------------------------
#define GEMM_MAIN(AH, AL, BH_, BL_)                                            \
    __shared__ __nv_bfloat16 sA[2][128][40];                                   \
    __shared__ __nv_bfloat16 sB[2][32][136];                                   \
    const int tid = threadIdx.x, lane = tid & 31, warp = tid >> 5;             \
    const int wm = warp >> 2, wn = warp & 3;                                   \
    const int row0 = blockIdx.y * 128, col0 = blockIdx.x * 128;                \
    float acc[4][4][4];                                                        \
    _Pragma("unroll") for (int i = 0; i < 4; i++)                              \
    _Pragma("unroll") for (int j = 0; j < 4; j++)                              \
    _Pragma("unroll") for (int f = 0; f < 4; f++) acc[i][j][f] = 0.f;          \
    const int ar = tid >> 1, ac = (tid & 1) * 16;                              \
    const int br = tid >> 3, bc = (tid & 7) * 8;                               \
    {                                                                          \
        uint4 a0 = *(const uint4*)(AH + (size_t)(row0 + ar) * DM + ac);        \
        uint4 a1 = *(const uint4*)(AH + (size_t)(row0 + ar) * DM + ac + 8);    \
        uint4 b0 = *(const uint4*)(BH_ + (size_t)br * DM + col0 + bc);         \
        uint4 b1 = *(const uint4*)(BH_ + (size_t)br * DM + col0 + bc + 64);    \
        *(uint4*)&sA[0][ar][ac] = a0;  *(uint4*)&sA[0][ar][ac + 8] = a1;       \
        *(uint4*)&sB[0][br][bc] = b0;  *(uint4*)&sB[0][br][bc + 64] = b1;      \
    }                                                                          \
    __syncthreads();                                                           \
    int buf = 0;                                                               \
    for (int cc = 0; cc < 96; cc++) {                                          \
        uint4 a0, a1, b0, b1;                                                  \
        const bool nxt = (cc + 1) < 96;                                        \
        if (nxt) {                                                             \
            int ph = (cc + 1) >> 5, k0 = ((cc + 1) & 31) * 32;                 \
            const __nv_bfloat16* Ap = (ph == 1) ? AL : AH;                     \
            const __nv_bfloat16* Bp = (ph == 2) ? BL_ : BH_;                   \
            a0 = *(const uint4*)(Ap + (size_t)(row0 + ar) * DM + k0 + ac);     \
            a1 = *(const uint4*)(Ap + (size_t)(row0 + ar) * DM + k0 + ac + 8); \
            b0 = *(const uint4*)(Bp + (size_t)(k0 + br) * DM + col0 + bc);     \
            b1 = *(const uint4*)(Bp + (size_t)(k0 + br) * DM + col0 + bc + 64);\
        }                                                                      \
        _Pragma("unroll")                                                      \
        for (int ks = 0; ks < 32; ks += 16) {                                  \
            uint32_t afr[4][4], bfr[4][2];                                     \
            _Pragma("unroll")                                                  \
            for (int i = 0; i < 4; i++) {                                      \
                uint32_t ad = smem_u32(                                        \
                    &sA[buf][wm * 64 + i * 16 + (lane & 15)]                   \
                        [ks + (lane >> 4) * 8]);                               \
                LDSM_X4(afr[i], ad);                                           \
            }                                                                  \
            _Pragma("unroll")                                                  \
            for (int j = 0; j < 4; j++) {                                      \
                uint32_t bd = smem_u32(                                        \
                    &sB[buf][ks + (lane & 15)][wn * 32 + j * 8]);              \
                LDSM_X2T(bfr[j], bd);                                          \
            }                                                                  \
            _Pragma("unroll")                                                  \
            for (int i = 0; i < 4; i++)                                        \
            _Pragma("unroll")                                                  \
            for (int j = 0; j < 4; j++) MMA_STEP(afr[i], bfr[j], acc[i][j]);   \
        }                                                                      \
        if (nxt) {                                                             \
            *(uint4*)&sA[buf ^ 1][ar][ac] = a0;                                \
            *(uint4*)&sA[buf ^ 1][ar][ac + 8] = a1;                            \
            *(uint4*)&sB[buf ^ 1][br][bc] = b0;                                \
            *(uint4*)&sB[buf ^ 1][br][bc + 64] = b1;                           \
        }                                                                      \
        __syncthreads();                                                       \
        buf ^= 1;                                                              \
    }

// QKV: writes bf16 hi/lo splits directly (Q pre-scaled by 0.125)
__global__ __launch_bounds__(256) void qkv_mma_kernel()
{
    const int z = blockIdx.z;
    const __nv_bfloat16* BHp = g_Wh[z];
    const __nv_bfloat16* BLp = g_Wl[z];

    GEMM_MAIN(g_Xh, g_Xl, BHp, BLp)

    __nv_bfloat16* Oh = (z == 0) ? g_Qh : (z == 1) ? g_Kh : g_Vh;
    __nv_bfloat16* Ol = (z == 0) ? g_Ql : (z == 1) ? g_Kl : g_Vl;
    const float sc = (z == 0) ? 0.125f : 1.0f;

    const int lr = lane >> 2, lc = (lane & 3) * 2;
#pragma unroll
    for (int i = 0; i < 4; i++) {
        int r0 = row0 + wm * 64 + i * 16 + lr;
#pragma unroll
        for (int j = 0; j < 4; j++) {
            int c = col0 + wn * 32 + j * 8 + lc;
            int h_ = c >> 6, d_ = c & 63;
#pragma unroll
            for (int hrow = 0; hrow < 2; hrow++) {
                int r = r0 + hrow * 8;
                int b_ = r >> 10, l_ = r & 1023;
                float v0 = acc[i][j][hrow * 2 + 0] * sc;
                float v1 = acc[i][j][hrow * 2 + 1] * sc;
                __nv_bfloat16 h0 = __float2bfloat16(v0);
                __nv_bfloat16 h1 = __float2bfloat16(v1);
                size_t off = (((size_t)(b_ * H + h_)) * L + l_) * DK + d_;
                *(__nv_bfloat162*)(Oh + off) = __nv_bfloat162(h0, h1);
                *(__nv_bfloat162*)(Ol + off) = __nv_bfloat162(
                    __float2bfloat16(v0 - __bfloat162float(h0)),
                    __float2bfloat16(v1 - __bfloat162float(h1)));
            }
        }
    }
}

__global__ __launch_bounds__(256) void oproj_mma_kernel(const float* __restrict__ X)
{
    GEMM_MAIN(g_Ch, g_Cl, g_Wh[3], g_Wl[3])

    const int lr = lane >> 2, lc = (lane & 3) * 2;
#pragma unroll
    for (int i = 0; i < 4; i++) {
        int r0 = row0 + wm * 64 + i * 16 + lr;
#pragma unroll
        for (int j = 0; j < 4; j++) {
            int c = col0 + wn * 32 + j * 8 + lc;
#pragma unroll
            for (int hrow = 0; hrow < 2; hrow++) {
                int r = r0 + hrow * 8;
                float2 xv = *(const float2*)&X[(size_t)r * DM + c];
                float2 o;
                o.x = acc[i][j][hrow * 2 + 0] + xv.x;
                o.y = acc[i][j][hrow * 2 + 1] + xv.y;
                *(float2*)&g_preln[(size_t)r * DM + c] = o;
            }
        }
    }
}

// ---------------- tensor-core attention (cp.async pipelined) -----------------
// Block = (bh, 32 q rows), 256 thr / 8 warps (wm 2 x wn 4).
// smem: S[32][1028] f32 | Q hi/lo [32][72] | KV 2 bufs x (hi+lo [64][72])
//       | P 2 bufs x (hi+lo [32][136])
#define SOFF_Q   131584
#define SOFF_KV  140800
#define KVBUF    18432          // bytes per KV buffer (hi 9216 + lo 9216)
#define SOFF_P   177664
#define PBUF     17408          // bytes per P buffer (hi 8704 + lo 8704)
#define ATTN_SMEM 212480

__global__ __launch_bounds__(256) void attn_mma_kernel(
    const void* __restrict__ mask, float* __restrict__ attn_out)
{
    extern __shared__ char smx[];
    float* S = (float*)smx;
    __nv_bfloat16* Qsh = (__nv_bfloat16*)(smx + SOFF_Q);
    __nv_bfloat16* Qsl = Qsh + 32 * 72;

    const int tid = threadIdx.x, lane = tid & 31, warp = tid >> 5;
    const int wm = warp >> 2, wn = warp & 3;
    const int bh = blockIdx.y, b_ = bh >> 4, q0 = blockIdx.x * 32;
    const int u8 = g_mask_u8;
    const uint32_t sb = smem_u32(smx);

    // async load of a 64-row KV chunk (hi+lo), 4 cp16 per thread
    auto load_kv = [&](const __nv_bfloat16* Gh, const __nv_bfloat16* Gl,
                       int kc, int bu) {
        uint32_t base = sb + SOFF_KV + bu * KVBUF;
#pragma unroll
        for (int i = 0; i < 2; i++) {
            int idx = i * 256 + tid;
            int r = idx >> 3, cb = idx & 7;
            cp16(base + r * 144 + cb * 16,
                 Gh + ((size_t)bh * L + kc + r) * DK + cb * 8);
            cp16(base + 9216 + r * 144 + cb * 16,
                 Gl + ((size_t)bh * L + kc + r) * DK + cb * 8);
        }
        CP_COMMIT();
    };

    // ---- Q smem fill + fragments ----
    {
        int r = tid >> 3, d0 = (tid & 7) * 8;
        *(uint4*)(Qsh + r * 72 + d0) =
            *(const uint4*)(g_Qh + ((size_t)bh * L + q0 + r) * DK + d0);
        *(uint4*)(Qsl + r * 72 + d0) =
            *(const uint4*)(g_Ql + ((size_t)bh * L + q0 + r) * DK + d0);
    }
    load_kv(g_Kh, g_Kl, 0, 0);
    __syncthreads();

    uint32_t qfh[4][4], qfl[4][4];
#pragma unroll
    for (int kk = 0; kk < 4; kk++) {
        uint32_t ad = smem_u32(Qsh + (wm * 16 + (lane & 15)) * 72 +
                               kk * 16 + (lane >> 4) * 8);
        LDSM_X4(qfh[kk], ad);
        ad = smem_u32(Qsl + (wm * 16 + (lane & 15)) * 72 +
                      kk * 16 + (lane >> 4) * 8);
        LDSM_X4(qfl[kk], ad);
    }

    // ---- score phase: 16 chunks of 64 keys, double-buffered ----
    for (int c = 0; c < 16; c++) {
        int bu = c & 1;
        CP_WAIT0();
        __syncthreads();
        if (c + 1 < 16) load_kv(g_Kh, g_Kl, (c + 1) * 64, bu ^ 1);

        const __nv_bfloat16* KBh = (const __nv_bfloat16*)(smx + SOFF_KV + bu * KVBUF);
        const __nv_bfloat16* KBl = KBh + 4608;

        float acc[2][4];
#pragma unroll
        for (int t = 0; t < 2; t++)
#pragma unroll
            for (int f = 0; f < 4; f++) acc[t][f] = 0.f;

#pragma unroll
        for (int kk = 0; kk < 4; kk++) {
            uint32_t bfh[2][2], bfl[2][2];
#pragma unroll
            for (int t = 0; t < 2; t++) {
                int kb = wn * 16 + t * 8;
                uint32_t ad = smem_u32(KBh + (kb + (lane & 7)) * 72 +
                                       kk * 16 + ((lane >> 3) & 1) * 8);
                LDSM_X2(bfh[t], ad);
                ad = smem_u32(KBl + (kb + (lane & 7)) * 72 +
                              kk * 16 + ((lane >> 3) & 1) * 8);
                LDSM_X2(bfl[t], ad);
            }
#pragma unroll
            for (int t = 0; t < 2; t++) MMA_STEP(qfh[kk], bfh[t], acc[t]);
#pragma unroll
            for (int t = 0; t < 2; t++) MMA_STEP(qfl[kk], bfh[t], acc[t]);
#pragma unroll
            for (int t = 0; t < 2; t++) MMA_STEP(qfh[kk], bfl[t], acc[t]);
        }

        int row = wm * 16 + (lane >> 2);
#pragma unroll
        for (int t = 0; t < 2; t++) {
            int col = c * 64 + wn * 16 + t * 8 + 2 * (lane & 3);
            *(float2*)&S[row * 1028 + col] = make_float2(acc[t][0], acc[t][1]);
            *(float2*)&S[(row + 8) * 1028 + col] = make_float2(acc[t][2], acc[t][3]);
        }
    }
    __syncthreads();

    // ---- mask + softmax + normalize + attn_out: float4 vectorized ----------
    {
        const int row = tid >> 3, c0 = tid & 7;
        float* Sr = S + row * 1028;
        size_t mbase = ((size_t)b_ * L + q0 + row) * L;

        float mx = -3.4e38f;
        if (u8) {
            const unsigned char* m8 = (const unsigned char*)mask + mbase;
#pragma unroll 4
            for (int k = 0; k < 32; k++) {
                int c = (c0 + 8 * k) * 4;
                float4 v = *(float4*)&Sr[c];
                uint32_t mw = *(const uint32_t*)(m8 + c);
                if (mw & 0x000000ffu) v.x = -1e9f;
                if (mw & 0x0000ff00u) v.y = -1e9f;
                if (mw & 0x00ff0000u) v.z = -1e9f;
                if (mw & 0xff000000u) v.w = -1e9f;
                *(float4*)&Sr[c] = v;
                mx = fmaxf(mx, fmaxf(fmaxf(v.x, v.y), fmaxf(v.z, v.w)));
            }
        } else {
            const int* m32 = (const int*)mask + mbase;
#pragma unroll 4
            for (int k = 0; k < 32; k++) {
                int c = (c0 + 8 * k) * 4;
                float4 v = *(float4*)&Sr[c];
                int4 mw = *(const int4*)(m32 + c);
                if (mw.x) v.x = -1e9f;
                if (mw.y) v.y = -1e9f;
                if (mw.z) v.z = -1e9f;
                if (mw.w) v.w = -1e9f;
                *(float4*)&Sr[c] = v;
                mx = fmaxf(mx, fmaxf(fmaxf(v.x, v.y), fmaxf(v.z, v.w)));
            }
        }
#pragma unroll
        for (int off = 4; off; off >>= 1)
            mx = fmaxf(mx, __shfl_xor_sync(0xffffffffu, mx, off));

        float sum = 0.f;
#pragma unroll 4
        for (int k = 0; k < 32; k++) {
            int c = (c0 + 8 * k) * 4;
            float4 v = *(float4*)&Sr[c];
            v.x = __expf(v.x - mx);
            v.y = __expf(v.y - mx);
            v.z = __expf(v.z - mx);
            v.w = __expf(v.w - mx);
            *(float4*)&Sr[c] = v;
            sum += v.x + v.y + v.z + v.w;
        }
#pragma unroll
        for (int off = 4; off; off >>= 1)
            sum += __shfl_xor_sync(0xffffffffu, sum, off);
        float inv = 1.f / sum;

        float* Ar = attn_out ? (attn_out + ((size_t)bh * L + q0 + row) * L) : nullptr;
#pragma unroll 4
        for (int k = 0; k < 32; k++) {
            int c = (c0 + 8 * k) * 4;
            float4 v = *(float4*)&Sr[c];
            v.x *= inv; v.y *= inv; v.z *= inv; v.w *= inv;
            *(float4*)&Sr[c] = v;
            if (Ar) *(float4*)&Ar[c] = v;
        }
    }

    // convert P chunk (64 cols at kc) into P buffer pb
    auto convP = [&](int kc, int pb) {
        __nv_bfloat16* Ph = (__nv_bfloat16*)(smx + SOFF_P + pb * PBUF);
        __nv_bfloat16* Pl = Ph + 32 * 136;
        int r = tid >> 3, cb = (tid & 7) * 8;
        const float* Sr = S + r * 1028 + kc + cb;
#pragma unroll
        for (int i = 0; i < 8; i += 4) {
            float4 p = *(const float4*)&Sr[i];
            __nv_bfloat16 h0 = __float2bfloat16(p.x);
            __nv_bfloat16 h1 = __float2bfloat16(p.y);
            __nv_bfloat16 h2 = __float2bfloat16(p.z);
            __nv_bfloat16 h3 = __float2bfloat16(p.w);
            __nv_bfloat162* php = (__nv_bfloat162*)(Ph + r * 136 + cb + i);
            php[0] = __nv_bfloat162(h0, h1);
            php[1] = __nv_bfloat162(h2, h3);
            __nv_bfloat162* plp = (__nv_bfloat162*)(Pl + r * 136 + cb + i);
            plp[0] = __nv_bfloat162(
                __float2bfloat16(p.x - __bfloat162float(h0)),
                __float2bfloat16(p.y - __bfloat162float(h1)));
            plp[1] = __nv_bfloat162(
                __float2bfloat16(p.z - __bfloat162float(h2)),
                __float2bfloat16(p.w - __bfloat162float(h3)));
        }
    };

    // ---- context phase: 16 chunks, double-buffered V + P ----
    float cacc[2][4];
#pragma unroll
    for (int t = 0; t < 2; t++)
#pragma unroll
        for (int f = 0; f < 4; f++) cacc[t][f] = 0.f;

    load_kv(g_Vh, g_Vl, 0, 0);
    convP(0, 0);

    for (int c = 0; c < 16; c++) {
        int bu = c & 1;
        CP_WAIT0();
        __syncthreads();
        if (c + 1 < 16) {
            load_kv(g_Vh, g_Vl, (c + 1) * 64, bu ^ 1);
            convP((c + 1) * 64, bu ^ 1);
        }

        const __nv_bfloat16* VBh = (const __nv_bfloat16*)(smx + SOFF_KV + bu * KVBUF);
        const __nv_bfloat16* VBl = VBh + 4608;
        const __nv_bfloat16* Ph = (const __nv_bfloat16*)(smx + SOFF_P + bu * PBUF);
        const __nv_bfloat16* Pl = Ph + 32 * 136;

#pragma unroll
        for (int kk = 0; kk < 4; kk++) {
            uint32_t pah[4], pal[4], bvh[2][2], bvl[2][2];
            uint32_t ad = smem_u32(Ph + (wm * 16 + (lane & 15)) * 136 +
                                   kk * 16 + (lane >> 4) * 8);
            LDSM_X4(pah, ad);
            ad = smem_u32(Pl + (wm * 16 + (lane & 15)) * 136 +
                          kk * 16 + (lane >> 4) * 8);
            LDSM_X4(pal, ad);
#pragma unroll
            for (int t = 0; t < 2; t++) {
                ad = smem_u32(VBh + (kk * 16 + (lane & 15)) * 72 +
                              wn * 16 + t * 8);
                LDSM_X2T(bvh[t], ad);
                ad = smem_u32(VBl + (kk * 16 + (lane & 15)) * 72 +
                              wn * 16 + t * 8);
                LDSM_X2T(bvl[t], ad);
            }
#pragma unroll
            for (int t = 0; t < 2; t++) MMA_STEP(pah, bvh[t], cacc[t]);
#pragma unroll
            for (int t = 0; t < 2; t++) MMA_STEP(pal, bvh[t], cacc[t]);
#pragma unroll
            for (int t = 0; t < 2; t++) MMA_STEP(pah, bvl[t], cacc[t]);
        }
    }

    // ---- write context as bf16 split 2D [B*L][1024] ----
    {
        int h_ = bh & 15;
        int row = q0 + wm * 16 + (lane >> 2);
#pragma unroll
        for (int t = 0; t < 2; t++) {
            int d = wn * 16 + t * 8 + 2 * (lane & 3);
#pragma unroll
            for (int hrow = 0; hrow < 2; hrow++) {
                float v0 = cacc[t][hrow * 2 + 0];
                float v1 = cacc[t][hrow * 2 + 1];
                __nv_bfloat16 h0 = __float2bfloat16(v0);
                __nv_bfloat16 h1 = __float2bfloat16(v1);
                size_t off = ((size_t)(b_ * L) + row + hrow * 8) * DM + h_ * 64 + d;
                *(__nv_bfloat162*)(g_Ch + off) = __nv_bfloat162(h0, h1);
                *(__nv_bfloat162*)(g_Cl + off) = __nv_bfloat162(
                    __float2bfloat16(v0 - __bfloat162float(h0)),
                    __float2bfloat16(v1 - __bfloat162float(h1)));
            }
        }
    }
}

// ---------------- layernorm --------------------------------------------------
__global__ __launch_bounds__(256) void ln_kernel(
    const float* __restrict__ gamma, const float* __restrict__ beta,
    float* __restrict__ out)
{
    __shared__ float red[18];
    const int r = blockIdx.x, tid = threadIdx.x;
    const float4* x4 = (const float4*)(g_preln + (size_t)r * DM);
    float4 v = x4[tid];

    float s = v.x + v.y + v.z + v.w;
#pragma unroll
    for (int off = 16; off; off >>= 1) s += __shfl_xor_sync(0xffffffffu, s, off);
    if ((tid & 31) == 0) red[tid >> 5] = s;
    __syncthreads();
    if (tid == 0) {
        float t = 0.f;
        for (int i = 0; i < 8; i++) t += red[i];
        red[16] = t * (1.f / 1024.f);
    }
    __syncthreads();
    float mean = red[16];

    float dx = v.x - mean, dy = v.y - mean, dz = v.z - mean, dw = v.w - mean;
    float ss = dx * dx + dy * dy + dz * dz + dw * dw;
#pragma unroll
    for (int off = 16; off; off >>= 1) ss += __shfl_xor_sync(0xffffffffu, ss, off);
    if ((tid & 31) == 0) red[8 + (tid >> 5)] = ss;
    __syncthreads();
    if (tid == 0) {
        float t = 0.f;
        for (int i = 0; i < 8; i++) t += red[8 + i];
        red[17] = rsqrtf(t * (1.f / 1024.f) + 1e-6f);
    }
    __syncthreads();
    float rs = red[17];

    float4 g = ((const float4*)gamma)[tid];
    float4 bb = ((const float4*)beta)[tid];
    float4 o;
    o.x = dx * rs * g.x + bb.x;
    o.y = dy * rs * g.y + bb.y;
    o.z = dz * rs * g.z + bb.z;
    o.w = dw * rs * g.w + bb.w;

    float* op = out ? (out + (size_t)r * DM) : (g_preln + (size_t)r * DM);
    ((float4*)op)[tid] = o;
}

// ---------------- launch -----------------------------------------------------
extern "C" void kernel_launch(void* const* d_in, const int* in_sizes, int n_in,
                              void* d_out, int out_size)
{
    const float* X     = (const float*)d_in[0];
    const void*  mask  = d_in[1];
    const float* Wq    = (const float*)d_in[2];
    const float* Wk    = (const float*)d_in[3];
    const float* Wv    = (const float*)d_in[4];
    const float* Wo    = (const float*)d_in[5];
    const float* gamma = (const float*)d_in[6];
    const float* beta  = (const float*)d_in[7];

    const long long LNN = (long long)B * L * DM;
    const long long ATT = (long long)BH * L * L;

    float* out_ln = nullptr;
    float* out_attn = nullptr;
    long long os = (long long)out_size;
    if (os >= LNN + ATT) {
        out_ln = (float*)d_out;
        out_attn = (float*)d_out + LNN;
    } else if (os == ATT) {
        out_attn = (float*)d_out;
    } else {
        out_ln = (float*)d_out;
    }

    detect_mask_kernel<<<1, 256>>>((const unsigned int*)mask);

    __nv_bfloat16 *Xh, *Xl, *Wh0, *Wl0;
    cudaGetSymbolAddress((void**)&Xh, g_Xh);
    cudaGetSymbolAddress((void**)&Xl, g_Xl);
    cudaGetSymbolAddress((void**)&Wh0, g_Wh);
    cudaGetSymbolAddress((void**)&Wl0, g_Wl);

    int nX4 = (B * L * DM) / 4;
    int nW4 = (DM * DM) / 4;
    cvt_split_kernel<<<(nX4 + 255) / 256, 256>>>((const float4*)X, Xh, Xl, nX4);
    cvt_split_kernel<<<(nW4 + 255) / 256, 256>>>((const float4*)Wq,
        Wh0 + 0 * (size_t)DM * DM, Wl0 + 0 * (size_t)DM * DM, nW4);
    cvt_split_kernel<<<(nW4 + 255) / 256, 256>>>((const float4*)Wk,
        Wh0 + 1 * (size_t)DM * DM, Wl0 + 1 * (size_t)DM * DM, nW4);
    cvt_split_kernel<<<(nW4 + 255) / 256, 256>>>((const float4*)Wv,
        Wh0 + 2 * (size_t)DM * DM, Wl0 + 2 * (size_t)DM * DM, nW4);
    cvt_split_kernel<<<(nW4 + 255) / 256, 256>>>((const float4*)Wo,
        Wh0 + 3 * (size_t)DM * DM, Wl0 + 3 * (size_t)DM * DM, nW4);

    qkv_mma_kernel<<<dim3(8, 64, 3), 256>>>();

    cudaFuncSetAttribute(attn_mma_kernel,
                         cudaFuncAttributeMaxDynamicSharedMemorySize, ATTN_SMEM);
    attn_mma_kernel<<<dim3(L / 32, BH), 256, ATTN_SMEM>>>(mask, out_attn);

    oproj_mma_kernel<<<dim3(8, 64), 256>>>(X);
    ln_kernel<<<B * L, 256>>>(gamma, beta, out_ln);
}